// round 1
// baseline (speedup 1.0000x reference)
#include <cuda_runtime.h>
#include <math.h>

#define Bb   8
#define Cch  512
#define Hh   64
#define Wwid 64
#define Nn   4096
#define NHh  8
#define Dd   64

// ---------------- scratch (device globals; no allocation allowed) ------------
__device__ float g_qn  [Bb*Cch*Nn];  // normalized q , layout (b, c, n)
__device__ float g_kvn [Bb*Cch*Nn];  // normalized kv, layout (b, c, n)
__device__ float g_Q   [Bb*Nn*Cch];  // (b, n, c) after rope
__device__ float g_K   [Bb*Nn*Cch];
__device__ float g_V   [Bb*Nn*Cch];
__device__ float g_attn[Bb*Nn*Cch];  // attention output, (b, n, c)
__device__ float g_rope[Nn*Dd];      // per n: [sin,cos] interleaved over d

// ---------------- rope table -------------------------------------------------
__global__ void rope_fill() {
    int idx = blockIdx.x * blockDim.x + threadIdx.x;   // 4096*32 threads
    int n = idx >> 5;
    int j = idx & 31;
    float inv = 1.0f / powf(10000.0f, (float)(2 * j) / 64.0f);
    float ang = (float)n * inv;
    g_rope[n * 64 + 2 * j]     = sinf(ang);
    g_rope[n * 64 + 2 * j + 1] = cosf(ang);
}

// ---------------- layernorm over C (strided), (B,C,N) -> (B,C,N) -------------
__global__ void ln_kernel(const float* __restrict__ x,
                          const float* __restrict__ gam,
                          const float* __restrict__ bet,
                          float* __restrict__ out) {
    __shared__ float gs[512], bs[512];
    int tid = threadIdx.x;                      // 128 threads
    for (int c = tid; c < 512; c += 128) { gs[c] = gam[c]; bs[c] = bet[c]; }
    __syncthreads();
    int b = blockIdx.y;
    int n = blockIdx.x * 128 + tid;
    const float* xp = x + (size_t)b * Cch * Nn + n;
    float s = 0.f, sq = 0.f;
#pragma unroll 8
    for (int c = 0; c < 512; c++) {
        float v = xp[(size_t)c * Nn];
        s += v; sq += v * v;
    }
    float mu   = s * (1.0f / 512.0f);
    float var  = sq * (1.0f / 512.0f) - mu * mu;
    float rstd = rsqrtf(var + 1e-5f);
    float* op = out + (size_t)b * Cch * Nn + n;
#pragma unroll 8
    for (int c = 0; c < 512; c++) {
        float v = xp[(size_t)c * Nn];
        op[(size_t)c * Nn] = (v - mu) * rstd * gs[c] + bs[c];
    }
}

// ---------------- QKV GEMM: Out[b,n,c] = sum_k X[b,k,n]*W[c,k] + bias[c] -----
// optional rope epilogue (Q, K). Tiles: 128n x 128c x 8k, 256 thr, 8x8/thread.
__global__ __launch_bounds__(256, 2)
void gemm_qkv(const float* __restrict__ X, const float* __restrict__ W,
              const float* __restrict__ bias, float* __restrict__ Out,
              int do_rope) {
    __shared__ float As[8][128];
    __shared__ float Bs[8][132];
    int tid = threadIdx.x;
    int b  = blockIdx.z;
    int c0 = blockIdx.x * 128;
    int n0 = blockIdx.y * 128;
    int tx = tid & 15, ty = tid >> 4;

    float acc[8][8];
#pragma unroll
    for (int i = 0; i < 8; i++)
#pragma unroll
        for (int j = 0; j < 8; j++) acc[i][j] = 0.f;

    const float* Xp = X + (size_t)b * Cch * Nn;
    int arow = tid >> 5, acol = (tid & 31) * 4;
    int brow = tid >> 1, bhalf = (tid & 1) * 4;

    for (int k0 = 0; k0 < 512; k0 += 8) {
        float4 av = *(const float4*)(Xp + (size_t)(k0 + arow) * Nn + n0 + acol);
        float4 bv = *(const float4*)(W + (size_t)(c0 + brow) * 512 + k0 + bhalf);
        *(float4*)(&As[arow][acol]) = av;
        Bs[bhalf + 0][brow] = bv.x;
        Bs[bhalf + 1][brow] = bv.y;
        Bs[bhalf + 2][brow] = bv.z;
        Bs[bhalf + 3][brow] = bv.w;
        __syncthreads();
#pragma unroll
        for (int kk = 0; kk < 8; kk++) {
            float a[8], bb[8];
#pragma unroll
            for (int i = 0; i < 8; i++) a[i] = As[kk][ty * 8 + i];
#pragma unroll
            for (int j = 0; j < 8; j++) bb[j] = Bs[kk][tx * 8 + j];
#pragma unroll
            for (int i = 0; i < 8; i++)
#pragma unroll
                for (int j = 0; j < 8; j++) acc[i][j] += a[i] * bb[j];
        }
        __syncthreads();
    }

    int cb = c0 + tx * 8;
    float bvals[8];
#pragma unroll
    for (int j = 0; j < 8; j++) bvals[j] = __ldg(bias + cb + j);

#pragma unroll
    for (int i = 0; i < 8; i++) {
        int n = n0 + ty * 8 + i;
        float v[8];
#pragma unroll
        for (int j = 0; j < 8; j++) v[j] = acc[i][j] + bvals[j];
        if (do_rope) {
            const float* rp = g_rope + n * 64;
#pragma unroll
            for (int jj = 0; jj < 4; jj++) {
                int d = (cb + 2 * jj) & 63;     // cb is 8-aligned -> d even
                float sn = rp[d], cs = rp[d + 1];
                float x0 = v[2 * jj], x1 = v[2 * jj + 1];
                v[2 * jj]     = x0 * cs - x1 * sn;
                v[2 * jj + 1] = x0 * sn + x1 * cs;
            }
        }
        float* op = Out + ((size_t)b * Nn + n) * Cch + cb;
        *(float4*)(op)     = make_float4(v[0], v[1], v[2], v[3]);
        *(float4*)(op + 4) = make_float4(v[4], v[5], v[6], v[7]);
    }
}

// ---------------- windowed attention: one block per (window, head) -----------
#define ATTN_SMEM ((4 * 64 * 65 + 256) * 4)
__global__ void attn_kernel(const float* __restrict__ bias_table) {
    extern __shared__ float sm[];
    float* Qs  = sm;                // 64*65
    float* Ks  = Qs + 64 * 65;
    float* Vs  = Ks + 64 * 65;
    float* Ps  = Vs + 64 * 65;      // scores / probs
    float* tbl = Ps + 64 * 65;      // 225

    int tid = threadIdx.x;          // 256 threads
    int w = blockIdx.x;             // 0..511 (b*64 + window)
    int h = blockIdx.y;             // head
    int b   = w >> 6;
    int win = w & 63;
    int wy = win >> 3, wx = win & 7;

    if (tid < 225) tbl[tid] = bias_table[tid * 8 + h];

    const size_t baseC = ((size_t)b * Nn) * Cch + h * 64;
    for (int e = tid; e < 4096; e += 256) {
        int i = e >> 6, d = e & 63;
        int ri = i >> 3, ci = i & 7;
        int n = (wy * 8 + ri) * 64 + wx * 8 + ci;
        size_t g = baseC + (size_t)n * Cch + d;
        Qs[i * 65 + d] = g_Q[g];
        Ks[i * 65 + d] = g_K[g];
        Vs[i * 65 + d] = g_V[g];
    }
    __syncthreads();

    // S = Q K^T * scale + bias
    for (int e = tid; e < 4096; e += 256) {
        int i = e >> 6, j = e & 63;
        float s = 0.f;
#pragma unroll 16
        for (int d = 0; d < 64; d++) s += Qs[i * 65 + d] * Ks[j * 65 + d];
        int ri = i >> 3, ci = i & 7, rj = j >> 3, cj = j & 7;
        int ridx = (ri - rj + 7) * 15 + (ci - cj + 7);
        Ps[i * 65 + j] = s * 0.125f + tbl[ridx];
    }
    __syncthreads();

    // softmax: warp per 8 rows
    int warp = tid >> 5, lane = tid & 31;
#pragma unroll
    for (int rr = 0; rr < 8; rr++) {
        int row = warp * 8 + rr;
        float v0 = Ps[row * 65 + lane];
        float v1 = Ps[row * 65 + lane + 32];
        float m = fmaxf(v0, v1);
#pragma unroll
        for (int o = 16; o > 0; o >>= 1) m = fmaxf(m, __shfl_xor_sync(0xffffffffu, m, o));
        float e0 = __expf(v0 - m), e1 = __expf(v1 - m);
        float s = e0 + e1;
#pragma unroll
        for (int o = 16; o > 0; o >>= 1) s += __shfl_xor_sync(0xffffffffu, s, o);
        float inv = 1.0f / s;
        Ps[row * 65 + lane]      = e0 * inv;
        Ps[row * 65 + lane + 32] = e1 * inv;
    }
    __syncthreads();

    // O = P V
    for (int e = tid; e < 4096; e += 256) {
        int i = e >> 6, d = e & 63;
        float s = 0.f;
#pragma unroll 16
        for (int j = 0; j < 64; j++) s += Ps[i * 65 + j] * Vs[j * 65 + d];
        int ri = i >> 3, ci = i & 7;
        int n = (wy * 8 + ri) * 64 + wx * 8 + ci;
        g_attn[baseC + (size_t)n * Cch + d] = s;
    }
}

// ---------------- output GEMM + bias + residual + implicit transpose ---------
// out[b,c,n] = sum_k attn[b,n,k]*Wo[c,k] + bo[c] + qn[b,c,n]
// tiles: 64c x 128n x 8k, 256 threads, 4x8/thread
__global__ __launch_bounds__(256)
void gemm_out(const float* __restrict__ Wo, const float* __restrict__ bo,
              float* __restrict__ out) {
    __shared__ float Ws[8][65];
    __shared__ float At[8][132];
    int tid = threadIdx.x;
    int b  = blockIdx.z;
    int n0 = blockIdx.x * 128;
    int c0 = blockIdx.y * 64;
    int tx = tid & 15, ty = tid >> 4;

    float acc[4][8];
#pragma unroll
    for (int i = 0; i < 4; i++)
#pragma unroll
        for (int j = 0; j < 8; j++) acc[i][j] = 0.f;

    const float* Ap = g_attn + (size_t)b * Nn * Cch;
    int wc = tid >> 2, wk = (tid & 3) * 2;
    int an = tid >> 1, ah = (tid & 1) * 4;

    for (int k0 = 0; k0 < 512; k0 += 8) {
        float2 wv = *(const float2*)(Wo + (size_t)(c0 + wc) * 512 + k0 + wk);
        float4 av = *(const float4*)(Ap + (size_t)(n0 + an) * 512 + k0 + ah);
        Ws[wk][wc] = wv.x;
        Ws[wk + 1][wc] = wv.y;
        At[ah + 0][an] = av.x;
        At[ah + 1][an] = av.y;
        At[ah + 2][an] = av.z;
        At[ah + 3][an] = av.w;
        __syncthreads();
#pragma unroll
        for (int kk = 0; kk < 8; kk++) {
            float a[4], bb[8];
#pragma unroll
            for (int i = 0; i < 4; i++) a[i] = Ws[kk][ty * 4 + i];
#pragma unroll
            for (int j = 0; j < 8; j++) bb[j] = At[kk][tx * 8 + j];
#pragma unroll
            for (int i = 0; i < 4; i++)
#pragma unroll
                for (int j = 0; j < 8; j++) acc[i][j] += a[i] * bb[j];
        }
        __syncthreads();
    }

#pragma unroll
    for (int i = 0; i < 4; i++) {
        int c = c0 + ty * 4 + i;
        float bc = __ldg(bo + c);
        size_t base = ((size_t)b * Cch + c) * Nn + n0 + tx * 8;
        float4 r0 = *(const float4*)(g_qn + base);
        float4 r1 = *(const float4*)(g_qn + base + 4);
        float4 o0 = make_float4(acc[i][0] + bc + r0.x, acc[i][1] + bc + r0.y,
                                acc[i][2] + bc + r0.z, acc[i][3] + bc + r0.w);
        float4 o1 = make_float4(acc[i][4] + bc + r1.x, acc[i][5] + bc + r1.y,
                                acc[i][6] + bc + r1.z, acc[i][7] + bc + r1.w);
        *(float4*)(out + base)     = o0;
        *(float4*)(out + base + 4) = o1;
    }
}

// ---------------- launch -----------------------------------------------------
extern "C" void kernel_launch(void* const* d_in, const int* in_sizes, int n_in,
                              void* d_out, int out_size) {
    const float* q          = (const float*)d_in[0];
    const float* kv         = (const float*)d_in[1];
    const float* gq         = (const float*)d_in[2];
    const float* bqln       = (const float*)d_in[3];
    const float* gkv        = (const float*)d_in[4];
    const float* bkvln      = (const float*)d_in[5];
    const float* Wq         = (const float*)d_in[6];
    const float* bq         = (const float*)d_in[7];
    const float* Wk         = (const float*)d_in[8];
    const float* bk         = (const float*)d_in[9];
    const float* Wv         = (const float*)d_in[10];
    const float* bv         = (const float*)d_in[11];
    const float* Wo         = (const float*)d_in[12];
    const float* bo         = (const float*)d_in[13];
    const float* bias_table = (const float*)d_in[14];
    float* out = (float*)d_out;

    float *p_qn, *p_kvn, *p_Q, *p_K, *p_V;
    cudaGetSymbolAddress((void**)&p_qn,  g_qn);
    cudaGetSymbolAddress((void**)&p_kvn, g_kvn);
    cudaGetSymbolAddress((void**)&p_Q,   g_Q);
    cudaGetSymbolAddress((void**)&p_K,   g_K);
    cudaGetSymbolAddress((void**)&p_V,   g_V);

    cudaFuncSetAttribute(attn_kernel,
                         cudaFuncAttributeMaxDynamicSharedMemorySize, ATTN_SMEM);

    rope_fill<<<512, 256>>>();

    ln_kernel<<<dim3(Nn / 128, Bb), 128>>>(q,  gq,  bqln,  p_qn);
    ln_kernel<<<dim3(Nn / 128, Bb), 128>>>(kv, gkv, bkvln, p_kvn);

    dim3 gq_grid(Cch / 128, Nn / 128, Bb);
    gemm_qkv<<<gq_grid, 256>>>(p_qn,  Wq, bq, p_Q, 1);
    gemm_qkv<<<gq_grid, 256>>>(p_kvn, Wk, bk, p_K, 1);
    gemm_qkv<<<gq_grid, 256>>>(p_kvn, Wv, bv, p_V, 0);

    attn_kernel<<<dim3(Bb * 64, NHh), 256, ATTN_SMEM>>>(bias_table);

    gemm_out<<<dim3(Nn / 128, Cch / 64, Bb), 256>>>(Wo, bo, out);
}

// round 4
// speedup vs baseline: 2.1178x; 2.1178x over previous
#include <cuda_runtime.h>
#include <cstdint>
#include <math.h>

#define Bb   8
#define Cch  512
#define Nn   4096
#define NHh  8
#define Dd   64

// ---------------- scratch ----------------------------------------------------
__device__ float g_qn  [Bb*Cch*Nn];  // normalized q , (b, c, n)  (residual)
__device__ float g_kvn [Bb*Cch*Nn];  // normalized kv, (b, c, n)
__device__ float g_qnt [Bb*Nn*Cch];  // normalized q , (b, n, c)
__device__ float g_kvnt[Bb*Nn*Cch];  // normalized kv, (b, n, c)
__device__ float g_Q   [Bb*Nn*Cch];  // (b, n, c) after rope
__device__ float g_K   [Bb*Nn*Cch];
__device__ float g_V   [Bb*Nn*Cch];
__device__ float g_attn[Bb*Nn*Cch];  // attention out, (b, n, c)
__device__ float g_rope[Nn*Dd];

__device__ __forceinline__ uint32_t cvt_tf32(float x) {
    uint32_t r; asm("cvt.rna.tf32.f32 %0, %1;" : "=r"(r) : "f"(x)); return r;
}
__device__ __forceinline__ void mma_tf32(float* d, const uint32_t* a, const uint32_t* b) {
    asm volatile(
        "mma.sync.aligned.m16n8k8.row.col.f32.tf32.tf32.f32 "
        "{%0,%1,%2,%3}, {%4,%5,%6,%7}, {%8,%9}, {%0,%1,%2,%3};"
        : "+f"(d[0]), "+f"(d[1]), "+f"(d[2]), "+f"(d[3])
        : "r"(a[0]), "r"(a[1]), "r"(a[2]), "r"(a[3]), "r"(b[0]), "r"(b[1]));
}

// smem: double-buffered A,B tiles; words, stride 36 per row of 32
#define TSTR 36
#define ABUF (128 * TSTR)                 // words per tile
#define GSMEM (4 * ABUF * 4)              // bytes: 2 bufs x (A+B)

// ---------------- mainloop: D[128m x 128c] = A[128x512] x W[128x512]^T -------
// acc[fm][j][q]; warp layout 4(m) x 2(n); warp tile 32m x 64n.
__device__ __forceinline__ void gemm_mainloop_mma(const float* __restrict__ A,
                                                  const float* __restrict__ W,
                                                  float* smem, float acc[2][8][4],
                                                  int m0, int c0) {
    uint32_t* sA[2] = { (uint32_t*)smem,              (uint32_t*)smem + 2 * ABUF };
    uint32_t* sB[2] = { (uint32_t*)smem + ABUF,       (uint32_t*)smem + 3 * ABUF };

    int tid = threadIdx.x;
    int wid = tid >> 5, lane = tid & 31;
    int gid = lane >> 2, tg = lane & 3;
    int warp_m = wid >> 1, warp_n = wid & 1;

    const float* Ap = A + (size_t)m0 * 512;
    const float* Wp = W + (size_t)c0 * 512;

    // per-thread global-load coords: 4 float4 each for A and B per stage
    int lrow = tid >> 3;            // 0..31 base row (x4 via p)
    int lk4  = (tid & 7) * 4;       // k offset (floats)

    // preload stage 0
    {
#pragma unroll
        for (int p = 0; p < 4; p++) {
            int r = p * 32 + lrow;
            float4 va = *(const float4*)(Ap + (size_t)r * 512 + lk4);
            float4 vb = *(const float4*)(Wp + (size_t)r * 512 + lk4);
            uint32_t* da = sA[0] + r * TSTR + lk4;
            uint32_t* db = sB[0] + r * TSTR + lk4;
            da[0] = cvt_tf32(va.x); da[1] = cvt_tf32(va.y); da[2] = cvt_tf32(va.z); da[3] = cvt_tf32(va.w);
            db[0] = cvt_tf32(vb.x); db[1] = cvt_tf32(vb.y); db[2] = cvt_tf32(vb.z); db[3] = cvt_tf32(vb.w);
        }
    }
    __syncthreads();

    for (int s = 0; s < 16; s++) {
        int buf = s & 1;
        float4 pa[4], pb[4];
        if (s < 15) {
            const float* Ap2 = Ap + (s + 1) * 32;
            const float* Wp2 = Wp + (s + 1) * 32;
#pragma unroll
            for (int p = 0; p < 4; p++) {
                int r = p * 32 + lrow;
                pa[p] = *(const float4*)(Ap2 + (size_t)r * 512 + lk4);
                pb[p] = *(const float4*)(Wp2 + (size_t)r * 512 + lk4);
            }
        }

        uint32_t* As = sA[buf];
        uint32_t* Bs = sB[buf];
#pragma unroll
        for (int kk = 0; kk < 4; kk++) {
            int kb = kk * 8;
            uint32_t af[2][4];
#pragma unroll
            for (int fm = 0; fm < 2; fm++) {
                int mrow = warp_m * 32 + fm * 16 + gid;
                af[fm][0] = As[(mrow    ) * TSTR + kb + tg];
                af[fm][1] = As[(mrow + 8) * TSTR + kb + tg];
                af[fm][2] = As[(mrow    ) * TSTR + kb + tg + 4];
                af[fm][3] = As[(mrow + 8) * TSTR + kb + tg + 4];
            }
#pragma unroll
            for (int j = 0; j < 8; j++) {
                int nrow = warp_n * 64 + j * 8 + gid;
                uint32_t bf[2];
                bf[0] = Bs[nrow * TSTR + kb + tg];
                bf[1] = Bs[nrow * TSTR + kb + tg + 4];
                mma_tf32(acc[0][j], af[0], bf);
                mma_tf32(acc[1][j], af[1], bf);
            }
        }

        if (s < 15) {
            uint32_t* da0 = sA[buf ^ 1];
            uint32_t* db0 = sB[buf ^ 1];
#pragma unroll
            for (int p = 0; p < 4; p++) {
                int r = p * 32 + lrow;
                uint32_t* da = da0 + r * TSTR + lk4;
                uint32_t* db = db0 + r * TSTR + lk4;
                da[0] = cvt_tf32(pa[p].x); da[1] = cvt_tf32(pa[p].y); da[2] = cvt_tf32(pa[p].z); da[3] = cvt_tf32(pa[p].w);
                db[0] = cvt_tf32(pb[p].x); db[1] = cvt_tf32(pb[p].y); db[2] = cvt_tf32(pb[p].z); db[3] = cvt_tf32(pb[p].w);
            }
        }
        __syncthreads();
    }
}

// ---------------- QKV projection (+bias, +rope), out (b,n,c) -----------------
__global__ __launch_bounds__(256)
void gemm_qkv_tc(const float* __restrict__ A, const float* __restrict__ W,
                 const float* __restrict__ bias, float* __restrict__ Out, int do_rope) {
    extern __shared__ float smem[];
    int m0 = blockIdx.x * 128, c0 = blockIdx.y * 128;
    float acc[2][8][4];
#pragma unroll
    for (int a = 0; a < 2; a++)
#pragma unroll
        for (int j = 0; j < 8; j++)
#pragma unroll
            for (int q = 0; q < 4; q++) acc[a][j][q] = 0.f;

    gemm_mainloop_mma(A, W, smem, acc, m0, c0);

    int tid = threadIdx.x;
    int wid = tid >> 5, lane = tid & 31;
    int gid = lane >> 2, tg = lane & 3;
    int warp_m = wid >> 1, warp_n = wid & 1;

#pragma unroll
    for (int fm = 0; fm < 2; fm++) {
#pragma unroll
        for (int rr = 0; rr < 2; rr++) {
            int m = m0 + warp_m * 32 + fm * 16 + gid + rr * 8;
            int n = m & (Nn - 1);
            float* orow = Out + (size_t)m * 512;
            const float* rp = g_rope + n * 64;
#pragma unroll
            for (int j = 0; j < 8; j++) {
                int col = c0 + warp_n * 64 + j * 8 + 2 * tg;
                float v0 = acc[fm][j][rr * 2]     + __ldg(bias + col);
                float v1 = acc[fm][j][rr * 2 + 1] + __ldg(bias + col + 1);
                if (do_rope) {
                    int d = (j * 8 + 2 * tg);
                    float sn = rp[d], cs = rp[d + 1];
                    float x0 = v0, x1 = v1;
                    v0 = x0 * cs - x1 * sn;
                    v1 = x0 * sn + x1 * cs;
                }
                *(float2*)(orow + col) = make_float2(v0, v1);
            }
        }
    }
}

// ---------------- output projection: (b,c,n) + bias + residual ---------------
#define SSTR 132
__global__ __launch_bounds__(256)
void gemm_out_tc(const float* __restrict__ A, const float* __restrict__ W,
                 const float* __restrict__ bo, const float* __restrict__ resid,
                 float* __restrict__ Out) {
    extern __shared__ float smem[];
    int m0 = blockIdx.x * 128, c0 = blockIdx.y * 128;
    float acc[2][8][4];
#pragma unroll
    for (int a = 0; a < 2; a++)
#pragma unroll
        for (int j = 0; j < 8; j++)
#pragma unroll
            for (int q = 0; q < 4; q++) acc[a][j][q] = 0.f;

    gemm_mainloop_mma(A, W, smem, acc, m0, c0);

    int tid = threadIdx.x;
    int wid = tid >> 5, lane = tid & 31;
    int gid = lane >> 2, tg = lane & 3;
    int warp_m = wid >> 1, warp_n = wid & 1;

    // stage D transposed: stage[c_local][m_local]
    float* stage = smem;
#pragma unroll
    for (int fm = 0; fm < 2; fm++) {
        int mb = warp_m * 32 + fm * 16 + gid;
#pragma unroll
        for (int j = 0; j < 8; j++) {
            int cl = warp_n * 64 + j * 8 + 2 * tg;
            stage[(cl    ) * SSTR + mb    ] = acc[fm][j][0];
            stage[(cl + 1) * SSTR + mb    ] = acc[fm][j][1];
            stage[(cl    ) * SSTR + mb + 8] = acc[fm][j][2];
            stage[(cl + 1) * SSTR + mb + 8] = acc[fm][j][3];
        }
    }
    __syncthreads();

    int b = m0 >> 12, n0 = m0 & (Nn - 1);
    for (int t = tid; t < 128 * 32; t += 256) {
        int cl = t >> 5, mq = (t & 31) * 4;
        int c = c0 + cl;
        float bc = __ldg(bo + c);
        size_t o = ((size_t)(b * 512 + c)) * 4096 + n0 + mq;
        float4 dv = *(float4*)(stage + cl * SSTR + mq);
        float4 rv = *(const float4*)(resid + o);
        *(float4*)(Out + o) = make_float4(dv.x + bc + rv.x, dv.y + bc + rv.y,
                                          dv.z + bc + rv.z, dv.w + bc + rv.w);
    }
}

// ---------------- rope table -------------------------------------------------
__global__ void rope_fill() {
    int idx = blockIdx.x * blockDim.x + threadIdx.x;
    int n = idx >> 5, j = idx & 31;
    float inv = 1.0f / powf(10000.0f, (float)(2 * j) / 64.0f);
    float ang = (float)n * inv;
    g_rope[n * 64 + 2 * j]     = sinf(ang);
    g_rope[n * 64 + 2 * j + 1] = cosf(ang);
}

// ---------------- layernorm (B,C,N) -> (B,C,N) -------------------------------
__global__ void ln_kernel(const float* __restrict__ x, const float* __restrict__ gam,
                          const float* __restrict__ bet, float* __restrict__ out) {
    __shared__ float gs[512], bs[512];
    int tid = threadIdx.x;
    for (int c = tid; c < 512; c += 128) { gs[c] = gam[c]; bs[c] = bet[c]; }
    __syncthreads();
    int b = blockIdx.y;
    int n = blockIdx.x * 128 + tid;
    const float* xp = x + (size_t)b * Cch * Nn + n;
    float s = 0.f, sq = 0.f;
#pragma unroll 8
    for (int c = 0; c < 512; c++) { float v = xp[(size_t)c * Nn]; s += v; sq += v * v; }
    float mu = s * (1.0f / 512.0f);
    float var = sq * (1.0f / 512.0f) - mu * mu;
    float rstd = rsqrtf(var + 1e-5f);
    float* op = out + (size_t)b * Cch * Nn + n;
#pragma unroll 8
    for (int c = 0; c < 512; c++) {
        float v = xp[(size_t)c * Nn];
        op[(size_t)c * Nn] = (v - mu) * rstd * gs[c] + bs[c];
    }
}

// ---------------- transpose (b,c,n) -> (b,n,c) -------------------------------
__global__ void transpose_cn_nc(const float* __restrict__ in, float* __restrict__ out) {
    __shared__ float t[32][33];
    int b = blockIdx.z;
    int n0 = blockIdx.x * 32, c0 = blockIdx.y * 32;
    int tx = threadIdx.x, ty = threadIdx.y;
    const float* ip = in + (size_t)b * Cch * Nn;
#pragma unroll
    for (int i = 0; i < 4; i++)
        t[ty + i * 8][tx] = ip[(size_t)(c0 + ty + i * 8) * Nn + n0 + tx];
    __syncthreads();
    float* op = out + (size_t)b * Nn * Cch;
#pragma unroll
    for (int i = 0; i < 4; i++)
        op[(size_t)(n0 + ty + i * 8) * Cch + c0 + tx] = t[tx][ty + i * 8];
}

// ---------------- windowed attention, 4x4 register tiling --------------------
#define APAD 68
#define ATTN_SMEM ((4 * 64 * APAD + 256) * 4)
__global__ __launch_bounds__(256) void attn_kernel(const float* __restrict__ bias_table) {
    extern __shared__ float sm[];
    float* Qs = sm;
    float* Ks = Qs + 64 * APAD;
    float* Vs = Ks + 64 * APAD;
    float* Ps = Vs + 64 * APAD;
    float* tbl = Ps + 64 * APAD;

    int tid = threadIdx.x;
    int w = blockIdx.x, h = blockIdx.y;
    int b = w >> 6, win = w & 63;
    int wy = win >> 3, wx = win & 7;
    if (tid < 225) tbl[tid] = bias_table[tid * 8 + h];

    const size_t baseC = ((size_t)b * Nn) * Cch + h * 64;
    for (int e = tid; e < 1024; e += 256) {
        int i = e >> 4, d4 = e & 15;
        int ri = i >> 3, ci = i & 7;
        int n = (wy * 8 + ri) * 64 + wx * 8 + ci;
        size_t g = baseC + (size_t)n * 512 + d4 * 4;
        *(float4*)&Qs[i * APAD + d4 * 4] = *(const float4*)(g_Q + g);
        *(float4*)&Ks[i * APAD + d4 * 4] = *(const float4*)(g_K + g);
        *(float4*)&Vs[i * APAD + d4 * 4] = *(const float4*)(g_V + g);
    }
    __syncthreads();

    int ti = tid >> 4, tj = tid & 15;
    int i0 = ti * 4, j0 = tj * 4;

    float acc[4][4] = {};
    for (int d4 = 0; d4 < 16; d4++) {
        float qv[4][4], kv[4][4];
#pragma unroll
        for (int r = 0; r < 4; r++) *(float4*)qv[r] = *(float4*)&Qs[(i0 + r) * APAD + d4 * 4];
#pragma unroll
        for (int r = 0; r < 4; r++) *(float4*)kv[r] = *(float4*)&Ks[(j0 + r) * APAD + d4 * 4];
#pragma unroll
        for (int a = 0; a < 4; a++)
#pragma unroll
            for (int c = 0; c < 4; c++)
#pragma unroll
                for (int d = 0; d < 4; d++) acc[a][c] += qv[a][d] * kv[c][d];
    }
#pragma unroll
    for (int a = 0; a < 4; a++) {
        int i = i0 + a, ri = i >> 3, ci = i & 7;
        float4 o;
        float* po = (float*)&o;
#pragma unroll
        for (int c = 0; c < 4; c++) {
            int j = j0 + c, rj = j >> 3, cj = j & 7;
            int ridx = (ri - rj + 7) * 15 + (ci - cj + 7);
            po[c] = acc[a][c] * 0.125f + tbl[ridx];
        }
        *(float4*)&Ps[i * APAD + j0] = o;
    }
    __syncthreads();

    int warp = tid >> 5, lane = tid & 31;
#pragma unroll
    for (int rr = 0; rr < 8; rr++) {
        int row = warp * 8 + rr;
        float v0 = Ps[row * APAD + lane];
        float v1 = Ps[row * APAD + lane + 32];
        float m = fmaxf(v0, v1);
#pragma unroll
        for (int o = 16; o > 0; o >>= 1) m = fmaxf(m, __shfl_xor_sync(0xffffffffu, m, o));
        float e0 = __expf(v0 - m), e1 = __expf(v1 - m);
        float s = e0 + e1;
#pragma unroll
        for (int o = 16; o > 0; o >>= 1) s += __shfl_xor_sync(0xffffffffu, s, o);
        float inv = 1.0f / s;
        Ps[row * APAD + lane]      = e0 * inv;
        Ps[row * APAD + lane + 32] = e1 * inv;
    }
    __syncthreads();

    int d0 = tj * 4;
    float oacc[4][4] = {};
    for (int j4 = 0; j4 < 16; j4++) {
        float pv[4][4], vv[4][4];
#pragma unroll
        for (int r = 0; r < 4; r++) *(float4*)pv[r] = *(float4*)&Ps[(i0 + r) * APAD + j4 * 4];
#pragma unroll
        for (int jj = 0; jj < 4; jj++) *(float4*)vv[jj] = *(float4*)&Vs[(j4 * 4 + jj) * APAD + d0];
#pragma unroll
        for (int r = 0; r < 4; r++)
#pragma unroll
            for (int c = 0; c < 4; c++)
#pragma unroll
                for (int jj = 0; jj < 4; jj++) oacc[r][c] += pv[r][jj] * vv[jj][c];
    }
#pragma unroll
    for (int r = 0; r < 4; r++) {
        int i = i0 + r, ri = i >> 3, ci = i & 7;
        int n = (wy * 8 + ri) * 64 + wx * 8 + ci;
        *(float4*)(g_attn + baseC + (size_t)n * 512 + d0) =
            make_float4(oacc[r][0], oacc[r][1], oacc[r][2], oacc[r][3]);
    }
}

// ---------------- launch -----------------------------------------------------
extern "C" void kernel_launch(void* const* d_in, const int* in_sizes, int n_in,
                              void* d_out, int out_size) {
    const float* q          = (const float*)d_in[0];
    const float* kv         = (const float*)d_in[1];
    const float* gq         = (const float*)d_in[2];
    const float* bqln       = (const float*)d_in[3];
    const float* gkv        = (const float*)d_in[4];
    const float* bkvln      = (const float*)d_in[5];
    const float* Wq         = (const float*)d_in[6];
    const float* bq         = (const float*)d_in[7];
    const float* Wk         = (const float*)d_in[8];
    const float* bk         = (const float*)d_in[9];
    const float* Wv         = (const float*)d_in[10];
    const float* bv         = (const float*)d_in[11];
    const float* Wo         = (const float*)d_in[12];
    const float* bo         = (const float*)d_in[13];
    const float* bias_table = (const float*)d_in[14];
    float* out = (float*)d_out;

    float *p_qn, *p_kvn, *p_qnt, *p_kvnt, *p_Q, *p_K, *p_V, *p_attn;
    cudaGetSymbolAddress((void**)&p_qn,   g_qn);
    cudaGetSymbolAddress((void**)&p_kvn,  g_kvn);
    cudaGetSymbolAddress((void**)&p_qnt,  g_qnt);
    cudaGetSymbolAddress((void**)&p_kvnt, g_kvnt);
    cudaGetSymbolAddress((void**)&p_Q,    g_Q);
    cudaGetSymbolAddress((void**)&p_K,    g_K);
    cudaGetSymbolAddress((void**)&p_V,    g_V);
    cudaGetSymbolAddress((void**)&p_attn, g_attn);

    cudaFuncSetAttribute(gemm_qkv_tc, cudaFuncAttributeMaxDynamicSharedMemorySize, GSMEM);
    cudaFuncSetAttribute(gemm_out_tc, cudaFuncAttributeMaxDynamicSharedMemorySize, GSMEM);
    cudaFuncSetAttribute(attn_kernel, cudaFuncAttributeMaxDynamicSharedMemorySize, ATTN_SMEM);

    rope_fill<<<512, 256>>>();

    ln_kernel<<<dim3(Nn / 128, Bb), 128>>>(q,  gq,  bqln,  p_qn);
    ln_kernel<<<dim3(Nn / 128, Bb), 128>>>(kv, gkv, bkvln, p_kvn);

    dim3 tgrid(Nn / 32, Cch / 32, Bb);
    transpose_cn_nc<<<tgrid, dim3(32, 8)>>>(p_qn,  p_qnt);
    transpose_cn_nc<<<tgrid, dim3(32, 8)>>>(p_kvn, p_kvnt);

    dim3 ggrid(Bb * Nn / 128, Cch / 128);
    gemm_qkv_tc<<<ggrid, 256, GSMEM>>>(p_qnt,  Wq, bq, p_Q, 1);
    gemm_qkv_tc<<<ggrid, 256, GSMEM>>>(p_kvnt, Wk, bk, p_K, 1);
    gemm_qkv_tc<<<ggrid, 256, GSMEM>>>(p_kvnt, Wv, bv, p_V, 0);

    attn_kernel<<<dim3(Bb * 64, NHh), 256, ATTN_SMEM>>>(bias_table);

    gemm_out_tc<<<ggrid, 256, GSMEM>>>(p_attn, Wo, bo, p_qn, out);
}

// round 5
// speedup vs baseline: 3.4855x; 1.6458x over previous
#include <cuda_runtime.h>
#include <cuda_fp16.h>
#include <cstdint>
#include <math.h>

#define Bb   8
#define Cch  512
#define Nn   4096
#define NHh  8
#define Dd   64

// ---------------- scratch ----------------------------------------------------
__device__ float  g_qn    [Bb*Cch*Nn];   // normalized q , (b,c,n) fp32 (residual)
__device__ float  g_kvn   [Bb*Cch*Nn];   // normalized kv, (b,c,n) fp32
__device__ __half g_qnt_h [Bb*Nn*Cch];   // normalized q , (b,n,c) half (GEMM A)
__device__ __half g_kvnt_h[Bb*Nn*Cch];
__device__ __half g_Qh    [Bb*Nn*Cch];   // (b,n,c) after rope
__device__ __half g_Kh    [Bb*Nn*Cch];
__device__ __half g_Vh    [Bb*Nn*Cch];
__device__ __half g_attn_h[Bb*Nn*Cch];   // attention out, (b,n,c)
__device__ __half g_Wh    [4*Cch*Cch];   // rounded weights: Wq,Wk,Wv,Wo
__device__ float  g_rope  [Nn*Dd];

// ---------------- PTX helpers ------------------------------------------------
__device__ __forceinline__ uint32_t smem_u32(const void* p) {
    uint32_t a;
    asm("{ .reg .u64 t; cvta.to.shared.u64 t, %1; cvt.u32.u64 %0, t; }" : "=r"(a) : "l"(p));
    return a;
}
__device__ __forceinline__ void cp16(uint32_t dst, const void* src) {
    asm volatile("cp.async.cg.shared.global [%0], [%1], 16;" :: "r"(dst), "l"(src));
}
#define CP_COMMIT() asm volatile("cp.async.commit_group;" ::: "memory")
#define CP_WAIT2()  asm volatile("cp.async.wait_group 2;" ::: "memory")

__device__ __forceinline__ void mma_f16(float* d, const uint32_t* a, const uint32_t* b) {
    asm volatile(
        "mma.sync.aligned.m16n8k16.row.col.f32.f16.f16.f32 "
        "{%0,%1,%2,%3}, {%4,%5,%6,%7}, {%8,%9}, {%0,%1,%2,%3};"
        : "+f"(d[0]), "+f"(d[1]), "+f"(d[2]), "+f"(d[3])
        : "r"(a[0]), "r"(a[1]), "r"(a[2]), "r"(a[3]), "r"(b[0]), "r"(b[1]));
}

// smem: 3 stages x (A tile 16KB + B tile 16KB) = 96KB.
// tile: 128 rows x 64 halves (=32 words). word(r, wc) = r*32 + ((wc>>2 ^ (r&7))<<2) + (wc&3)
#define STAGE_B 32768
#define GSMEM   (3 * STAGE_B)

__device__ __forceinline__ void issue_stage(uint32_t sbuf, const char* as, const char* ws,
                                            uint32_t w0) {
#pragma unroll
    for (int p = 0; p < 4; p++) {
        cp16(sbuf + w0 + p * 4096,         as + p * 32768);
        cp16(sbuf + 16384 + w0 + p * 4096, ws + p * 32768);
    }
}

// ---------------- mainloop: D[128m x 128c] = A[128x512] x W[128x512]^T (half)
__device__ __forceinline__ void gemm_mainloop_h(const __half* __restrict__ A,
                                                const __half* __restrict__ W,
                                                char* smem, float acc[2][8][4],
                                                int m0, int c0) {
    uint32_t sb = smem_u32(smem);
    int tid = threadIdx.x;
    int wid = tid >> 5, lane = tid & 31;
    int gid = lane >> 2, tg = lane & 3;
    int warp_m = wid >> 1, warp_n = wid & 1;

    const char* Ab = (const char*)(A + (size_t)m0 * 512);
    const char* Wb = (const char*)(W + (size_t)c0 * 512);
    int r0 = tid >> 3, c4 = tid & 7;
    uint32_t w0 = (uint32_t)(r0 * 128 + ((c4 ^ (r0 & 7)) << 4));   // bytes
    uint32_t so = (uint32_t)(r0 * 1024 + c4 * 16);                 // bytes

    issue_stage(sb,            Ab + so,       Wb + so,       w0); CP_COMMIT();
    issue_stage(sb + STAGE_B,  Ab + so + 128, Wb + so + 128, w0); CP_COMMIT();

    for (int s = 0; s < 8; s++) {
        if (s + 2 < 8)
            issue_stage(sb + ((s + 2) % 3) * STAGE_B,
                        Ab + so + (s + 2) * 128, Wb + so + (s + 2) * 128, w0);
        CP_COMMIT();
        CP_WAIT2();
        __syncthreads();

        const uint32_t* As = (const uint32_t*)(smem + (s % 3) * STAGE_B);
        const uint32_t* Bs = As + 4096;
#pragma unroll
        for (int kk = 0; kk < 4; kk++) {
            int w_lo = tg + kk * 8, w_hi = tg + 4 + kk * 8;
            uint32_t af[2][4];
#pragma unroll
            for (int fm = 0; fm < 2; fm++) {
                int mr  = warp_m * 32 + fm * 16 + gid;
                int mr8 = mr + 8;
                af[fm][0] = As[mr  * 32 + (((w_lo >> 2) ^ (mr  & 7)) << 2) + (w_lo & 3)];
                af[fm][1] = As[mr8 * 32 + (((w_lo >> 2) ^ (mr8 & 7)) << 2) + (w_lo & 3)];
                af[fm][2] = As[mr  * 32 + (((w_hi >> 2) ^ (mr  & 7)) << 2) + (w_hi & 3)];
                af[fm][3] = As[mr8 * 32 + (((w_hi >> 2) ^ (mr8 & 7)) << 2) + (w_hi & 3)];
            }
#pragma unroll
            for (int j = 0; j < 8; j++) {
                int nr = warp_n * 64 + j * 8 + gid;
                uint32_t bf[2];
                bf[0] = Bs[nr * 32 + (((w_lo >> 2) ^ (nr & 7)) << 2) + (w_lo & 3)];
                bf[1] = Bs[nr * 32 + (((w_hi >> 2) ^ (nr & 7)) << 2) + (w_hi & 3)];
                mma_f16(acc[0][j], af[0], bf);
                mma_f16(acc[1][j], af[1], bf);
            }
        }
        __syncthreads();
    }
}

// ---------------- QKV projection (+bias, +rope), half out (b,n,c) ------------
__global__ __launch_bounds__(256)
void gemm_qkv_h(const __half* __restrict__ A, const __half* __restrict__ W,
                const float* __restrict__ bias, __half* __restrict__ Out, int do_rope) {
    extern __shared__ char smem[];
    int m0 = blockIdx.x * 128, c0 = blockIdx.y * 128;
    float acc[2][8][4];
#pragma unroll
    for (int a = 0; a < 2; a++)
#pragma unroll
        for (int j = 0; j < 8; j++)
#pragma unroll
            for (int q = 0; q < 4; q++) acc[a][j][q] = 0.f;

    gemm_mainloop_h(A, W, smem, acc, m0, c0);

    int tid = threadIdx.x;
    int wid = tid >> 5, lane = tid & 31;
    int gid = lane >> 2, tg = lane & 3;
    int warp_m = wid >> 1, warp_n = wid & 1;

#pragma unroll
    for (int fm = 0; fm < 2; fm++) {
#pragma unroll
        for (int rr = 0; rr < 2; rr++) {
            int m = m0 + warp_m * 32 + fm * 16 + gid + rr * 8;
            int n = m & (Nn - 1);
            __half* orow = Out + (size_t)m * 512;
            const float* rp = g_rope + n * 64;
#pragma unroll
            for (int j = 0; j < 8; j++) {
                int col = c0 + warp_n * 64 + j * 8 + 2 * tg;
                float v0 = acc[fm][j][rr * 2]     + __ldg(bias + col);
                float v1 = acc[fm][j][rr * 2 + 1] + __ldg(bias + col + 1);
                if (do_rope) {
                    int d = (j * 8 + 2 * tg);
                    float sn = rp[d], cs = rp[d + 1];
                    float x0 = v0, x1 = v1;
                    v0 = x0 * cs - x1 * sn;
                    v1 = x0 * sn + x1 * cs;
                }
                *(__half2*)(orow + col) = __floats2half2_rn(v0, v1);
            }
        }
    }
}

// ---------------- output projection: fp32 (b,c,n) + bias + residual ----------
#define SSTR 132
__global__ __launch_bounds__(256)
void gemm_out_h(const __half* __restrict__ A, const __half* __restrict__ W,
                const float* __restrict__ bo, const float* __restrict__ resid,
                float* __restrict__ Out) {
    extern __shared__ char smem[];
    int m0 = blockIdx.x * 128, c0 = blockIdx.y * 128;
    float acc[2][8][4];
#pragma unroll
    for (int a = 0; a < 2; a++)
#pragma unroll
        for (int j = 0; j < 8; j++)
#pragma unroll
            for (int q = 0; q < 4; q++) acc[a][j][q] = 0.f;

    gemm_mainloop_h(A, W, smem, acc, m0, c0);

    int tid = threadIdx.x;
    int wid = tid >> 5, lane = tid & 31;
    int gid = lane >> 2, tg = lane & 3;
    int warp_m = wid >> 1, warp_n = wid & 1;

    float* stage = (float*)smem;
    __syncthreads();
#pragma unroll
    for (int fm = 0; fm < 2; fm++) {
        int mb = warp_m * 32 + fm * 16 + gid;
#pragma unroll
        for (int j = 0; j < 8; j++) {
            int cl = warp_n * 64 + j * 8 + 2 * tg;
            stage[(cl    ) * SSTR + mb    ] = acc[fm][j][0];
            stage[(cl + 1) * SSTR + mb    ] = acc[fm][j][1];
            stage[(cl    ) * SSTR + mb + 8] = acc[fm][j][2];
            stage[(cl + 1) * SSTR + mb + 8] = acc[fm][j][3];
        }
    }
    __syncthreads();

    int b = m0 >> 12, n0 = m0 & (Nn - 1);
    for (int t = tid; t < 128 * 32; t += 256) {
        int cl = t >> 5, mq = (t & 31) * 4;
        int c = c0 + cl;
        float bc = __ldg(bo + c);
        size_t o = ((size_t)(b * 512 + c)) * 4096 + n0 + mq;
        float4 dv = *(float4*)(stage + cl * SSTR + mq);
        float4 rv = *(const float4*)(resid + o);
        *(float4*)(Out + o) = make_float4(dv.x + bc + rv.x, dv.y + bc + rv.y,
                                          dv.z + bc + rv.z, dv.w + bc + rv.w);
    }
}

// ---------------- weight fp32 -> half ---------------------------------------
__global__ void w2h(const float* __restrict__ src, __half* __restrict__ dst) {
    int i = (blockIdx.x * 256 + threadIdx.x) * 4;
    float4 v = *(const float4*)(src + i);
    *(__half2*)(dst + i)     = __floats2half2_rn(v.x, v.y);
    *(__half2*)(dst + i + 2) = __floats2half2_rn(v.z, v.w);
}

// ---------------- rope table -------------------------------------------------
__global__ void rope_fill() {
    int idx = blockIdx.x * blockDim.x + threadIdx.x;
    int n = idx >> 5, j = idx & 31;
    float inv = 1.0f / powf(10000.0f, (float)(2 * j) / 64.0f);
    float ang = (float)n * inv;
    g_rope[n * 64 + 2 * j]     = sinf(ang);
    g_rope[n * 64 + 2 * j + 1] = cosf(ang);
}

// ---------------- layernorm (B,C,N) -> (B,C,N) fp32 --------------------------
__global__ void ln_kernel(const float* __restrict__ x, const float* __restrict__ gam,
                          const float* __restrict__ bet, float* __restrict__ out) {
    __shared__ float gs[512], bs[512];
    int tid = threadIdx.x;
    for (int c = tid; c < 512; c += 128) { gs[c] = gam[c]; bs[c] = bet[c]; }
    __syncthreads();
    int b = blockIdx.y;
    int n = blockIdx.x * 128 + tid;
    const float* xp = x + (size_t)b * Cch * Nn + n;
    float s = 0.f, sq = 0.f;
#pragma unroll 8
    for (int c = 0; c < 512; c++) { float v = xp[(size_t)c * Nn]; s += v; sq += v * v; }
    float mu = s * (1.0f / 512.0f);
    float var = sq * (1.0f / 512.0f) - mu * mu;
    float rstd = rsqrtf(var + 1e-5f);
    float* op = out + (size_t)b * Cch * Nn + n;
#pragma unroll 8
    for (int c = 0; c < 512; c++) {
        float v = xp[(size_t)c * Nn];
        op[(size_t)c * Nn] = (v - mu) * rstd * gs[c] + bs[c];
    }
}

// ---------------- transpose (b,c,n) fp32 -> (b,n,c) half (rn-rounded) --------
__global__ void transpose_cn_nc_h(const float* __restrict__ in, __half* __restrict__ out) {
    __shared__ float t[32][33];
    int b = blockIdx.z;
    int n0 = blockIdx.x * 32, c0 = blockIdx.y * 32;
    int tx = threadIdx.x, ty = threadIdx.y;
    const float* ip = in + (size_t)b * Cch * Nn;
#pragma unroll
    for (int i = 0; i < 4; i++)
        t[ty + i * 8][tx] = ip[(size_t)(c0 + ty + i * 8) * Nn + n0 + tx];
    __syncthreads();
    __half* op = out + (size_t)b * Nn * Cch;
#pragma unroll
    for (int i = 0; i < 4; i++)
        op[(size_t)(n0 + ty + i * 8) * Cch + c0 + tx] = __float2half_rn(t[tx][ty + i * 8]);
}

// ---------------- windowed attention, half in / half out ---------------------
#define APAD 68
#define ATTN_SMEM ((4 * 64 * APAD + 256) * 4)
__global__ __launch_bounds__(256) void attn_kernel(const float* __restrict__ bias_table) {
    extern __shared__ float sm[];
    float* Qs = sm;
    float* Ks = Qs + 64 * APAD;
    float* Vs = Ks + 64 * APAD;
    float* Ps = Vs + 64 * APAD;
    float* tbl = Ps + 64 * APAD;

    int tid = threadIdx.x;
    int w = blockIdx.x, h = blockIdx.y;
    int b = w >> 6, win = w & 63;
    int wy = win >> 3, wx = win & 7;
    if (tid < 225) tbl[tid] = bias_table[tid * 8 + h];

    const size_t baseC = ((size_t)b * Nn) * Cch + h * 64;
    for (int e = tid; e < 1024; e += 256) {
        int i = e >> 4, d4 = e & 15;
        int ri = i >> 3, ci = i & 7;
        int n = (wy * 8 + ri) * 64 + wx * 8 + ci;
        size_t g = baseC + (size_t)n * 512 + d4 * 4;
        uint2 rq = *(const uint2*)(g_Qh + g);
        uint2 rk = *(const uint2*)(g_Kh + g);
        uint2 rv = *(const uint2*)(g_Vh + g);
        float2 a0 = __half22float2(*(__half2*)&rq.x), a1 = __half22float2(*(__half2*)&rq.y);
        float2 b0 = __half22float2(*(__half2*)&rk.x), b1 = __half22float2(*(__half2*)&rk.y);
        float2 c0 = __half22float2(*(__half2*)&rv.x), c1 = __half22float2(*(__half2*)&rv.y);
        *(float4*)&Qs[i * APAD + d4 * 4] = make_float4(a0.x, a0.y, a1.x, a1.y);
        *(float4*)&Ks[i * APAD + d4 * 4] = make_float4(b0.x, b0.y, b1.x, b1.y);
        *(float4*)&Vs[i * APAD + d4 * 4] = make_float4(c0.x, c0.y, c1.x, c1.y);
    }
    __syncthreads();

    int ti = tid >> 4, tj = tid & 15;
    int i0 = ti * 4, j0 = tj * 4;

    float acc[4][4] = {};
    for (int d4 = 0; d4 < 16; d4++) {
        float qv[4][4], kv[4][4];
#pragma unroll
        for (int r = 0; r < 4; r++) *(float4*)qv[r] = *(float4*)&Qs[(i0 + r) * APAD + d4 * 4];
#pragma unroll
        for (int r = 0; r < 4; r++) *(float4*)kv[r] = *(float4*)&Ks[(j0 + r) * APAD + d4 * 4];
#pragma unroll
        for (int a = 0; a < 4; a++)
#pragma unroll
            for (int c = 0; c < 4; c++)
#pragma unroll
                for (int d = 0; d < 4; d++) acc[a][c] += qv[a][d] * kv[c][d];
    }
#pragma unroll
    for (int a = 0; a < 4; a++) {
        int i = i0 + a, ri = i >> 3, ci = i & 7;
        float4 o;
        float* po = (float*)&o;
#pragma unroll
        for (int c = 0; c < 4; c++) {
            int j = j0 + c, rj = j >> 3, cj = j & 7;
            int ridx = (ri - rj + 7) * 15 + (ci - cj + 7);
            po[c] = acc[a][c] * 0.125f + tbl[ridx];
        }
        *(float4*)&Ps[i * APAD + j0] = o;
    }
    __syncthreads();

    int warp = tid >> 5, lane = tid & 31;
#pragma unroll
    for (int rr = 0; rr < 8; rr++) {
        int row = warp * 8 + rr;
        float v0 = Ps[row * APAD + lane];
        float v1 = Ps[row * APAD + lane + 32];
        float m = fmaxf(v0, v1);
#pragma unroll
        for (int o = 16; o > 0; o >>= 1) m = fmaxf(m, __shfl_xor_sync(0xffffffffu, m, o));
        float e0 = __expf(v0 - m), e1 = __expf(v1 - m);
        float s = e0 + e1;
#pragma unroll
        for (int o = 16; o > 0; o >>= 1) s += __shfl_xor_sync(0xffffffffu, s, o);
        float inv = 1.0f / s;
        Ps[row * APAD + lane]      = e0 * inv;
        Ps[row * APAD + lane + 32] = e1 * inv;
    }
    __syncthreads();

    int d0 = tj * 4;
    float oacc[4][4] = {};
    for (int j4 = 0; j4 < 16; j4++) {
        float pv[4][4], vv[4][4];
#pragma unroll
        for (int r = 0; r < 4; r++) *(float4*)pv[r] = *(float4*)&Ps[(i0 + r) * APAD + j4 * 4];
#pragma unroll
        for (int jj = 0; jj < 4; jj++) *(float4*)vv[jj] = *(float4*)&Vs[(j4 * 4 + jj) * APAD + d0];
#pragma unroll
        for (int r = 0; r < 4; r++)
#pragma unroll
            for (int c = 0; c < 4; c++)
#pragma unroll
                for (int jj = 0; jj < 4; jj++) oacc[r][c] += pv[r][jj] * vv[jj][c];
    }
#pragma unroll
    for (int r = 0; r < 4; r++) {
        int i = i0 + r, ri = i >> 3, ci = i & 7;
        int n = (wy * 8 + ri) * 64 + wx * 8 + ci;
        __half2 h0 = __floats2half2_rn(oacc[r][0], oacc[r][1]);
        __half2 h1 = __floats2half2_rn(oacc[r][2], oacc[r][3]);
        uint2 pk;
        pk.x = *(uint32_t*)&h0;
        pk.y = *(uint32_t*)&h1;
        *(uint2*)(g_attn_h + baseC + (size_t)n * 512 + d0) = pk;
    }
}

// ---------------- launch -----------------------------------------------------
extern "C" void kernel_launch(void* const* d_in, const int* in_sizes, int n_in,
                              void* d_out, int out_size) {
    const float* q          = (const float*)d_in[0];
    const float* kv         = (const float*)d_in[1];
    const float* gq         = (const float*)d_in[2];
    const float* bqln       = (const float*)d_in[3];
    const float* gkv        = (const float*)d_in[4];
    const float* bkvln      = (const float*)d_in[5];
    const float* Wq         = (const float*)d_in[6];
    const float* bq         = (const float*)d_in[7];
    const float* Wk         = (const float*)d_in[8];
    const float* bk         = (const float*)d_in[9];
    const float* Wv         = (const float*)d_in[10];
    const float* bv         = (const float*)d_in[11];
    const float* Wo         = (const float*)d_in[12];
    const float* bo         = (const float*)d_in[13];
    const float* bias_table = (const float*)d_in[14];
    float* out = (float*)d_out;

    float  *p_qn, *p_kvn, *p_rope;
    __half *p_qnt, *p_kvnt, *p_Q, *p_K, *p_V, *p_attn, *p_Wh;
    cudaGetSymbolAddress((void**)&p_qn,   g_qn);
    cudaGetSymbolAddress((void**)&p_kvn,  g_kvn);
    cudaGetSymbolAddress((void**)&p_qnt,  g_qnt_h);
    cudaGetSymbolAddress((void**)&p_kvnt, g_kvnt_h);
    cudaGetSymbolAddress((void**)&p_Q,    g_Qh);
    cudaGetSymbolAddress((void**)&p_K,    g_Kh);
    cudaGetSymbolAddress((void**)&p_V,    g_Vh);
    cudaGetSymbolAddress((void**)&p_attn, g_attn_h);
    cudaGetSymbolAddress((void**)&p_Wh,   g_Wh);
    cudaGetSymbolAddress((void**)&p_rope, g_rope);
    (void)p_rope;

    cudaFuncSetAttribute(gemm_qkv_h, cudaFuncAttributeMaxDynamicSharedMemorySize, GSMEM);
    cudaFuncSetAttribute(gemm_out_h, cudaFuncAttributeMaxDynamicSharedMemorySize, GSMEM);
    cudaFuncSetAttribute(attn_kernel, cudaFuncAttributeMaxDynamicSharedMemorySize, ATTN_SMEM);

    const int WB = (Cch * Cch) / 4 / 256;      // 256 blocks per weight
    w2h<<<WB, 256>>>(Wq, p_Wh + 0 * Cch * Cch);
    w2h<<<WB, 256>>>(Wk, p_Wh + 1 * Cch * Cch);
    w2h<<<WB, 256>>>(Wv, p_Wh + 2 * Cch * Cch);
    w2h<<<WB, 256>>>(Wo, p_Wh + 3 * Cch * Cch);

    rope_fill<<<512, 256>>>();

    ln_kernel<<<dim3(Nn / 128, Bb), 128>>>(q,  gq,  bqln,  p_qn);
    ln_kernel<<<dim3(Nn / 128, Bb), 128>>>(kv, gkv, bkvln, p_kvn);

    dim3 tgrid(Nn / 32, Cch / 32, Bb);
    transpose_cn_nc_h<<<tgrid, dim3(32, 8)>>>(p_qn,  p_qnt);
    transpose_cn_nc_h<<<tgrid, dim3(32, 8)>>>(p_kvn, p_kvnt);

    dim3 ggrid(Bb * Nn / 128, Cch / 128);
    gemm_qkv_h<<<ggrid, 256, GSMEM>>>(p_qnt,  p_Wh + 0 * Cch * Cch, bq, p_Q, 1);
    gemm_qkv_h<<<ggrid, 256, GSMEM>>>(p_kvnt, p_Wh + 1 * Cch * Cch, bk, p_K, 1);
    gemm_qkv_h<<<ggrid, 256, GSMEM>>>(p_kvnt, p_Wh + 2 * Cch * Cch, bv, p_V, 0);

    attn_kernel<<<dim3(Bb * 64, NHh), 256, ATTN_SMEM>>>(bias_table);

    gemm_out_h<<<ggrid, 256, GSMEM>>>(p_attn, p_Wh + 3 * Cch * Cch, bo, p_qn, out);
}

// round 6
// speedup vs baseline: 4.7767x; 1.3704x over previous
#include <cuda_runtime.h>
#include <cuda_fp16.h>
#include <cstdint>
#include <math.h>

#define Bb   8
#define Cch  512
#define Nn   4096
#define NHh  8
#define Dd   64

// ---------------- scratch ----------------------------------------------------
__device__ float  g_qn    [Bb*Cch*Nn];   // normalized q , (b,c,n) fp32 (residual)
__device__ float  g_kvn   [Bb*Cch*Nn];   // normalized kv, (b,c,n) fp32
__device__ __half g_qnt_h [Bb*Nn*Cch];   // normalized q , (b,n,c) half
__device__ __half g_kvnt_h[Bb*Nn*Cch];
__device__ __half g_Qh    [Bb*Nn*Cch];   // (b,n,c) after rope
__device__ __half g_Kh    [Bb*Nn*Cch];
__device__ __half g_Vh    [Bb*Nn*Cch];
__device__ __half g_attn_h[Bb*Nn*Cch];   // attention out, (b,n,c)
__device__ __half g_Wh    [4*Cch*Cch];   // rounded weights
__device__ float  g_rope  [Nn*Dd];

// ---------------- PTX helpers ------------------------------------------------
__device__ __forceinline__ uint32_t smem_u32(const void* p) {
    uint32_t a;
    asm("{ .reg .u64 t; cvta.to.shared.u64 t, %1; cvt.u32.u64 %0, t; }" : "=r"(a) : "l"(p));
    return a;
}
__device__ __forceinline__ void cp16(uint32_t dst, const void* src) {
    asm volatile("cp.async.cg.shared.global [%0], [%1], 16;" :: "r"(dst), "l"(src));
}
#define CP_COMMIT() asm volatile("cp.async.commit_group;" ::: "memory")
#define CP_WAIT2()  asm volatile("cp.async.wait_group 2;" ::: "memory")
#define CP_WAIT0()  asm volatile("cp.async.wait_group 0;" ::: "memory")

__device__ __forceinline__ void mma_f16(float* d, const uint32_t* a, const uint32_t* b) {
    asm volatile(
        "mma.sync.aligned.m16n8k16.row.col.f32.f16.f16.f32 "
        "{%0,%1,%2,%3}, {%4,%5,%6,%7}, {%8,%9}, {%0,%1,%2,%3};"
        : "+f"(d[0]), "+f"(d[1]), "+f"(d[2]), "+f"(d[3])
        : "r"(a[0]), "r"(a[1]), "r"(a[2]), "r"(a[3]), "r"(b[0]), "r"(b[1]));
}
__device__ __forceinline__ void ldsm4(uint32_t* r, uint32_t addr) {
    asm volatile("ldmatrix.sync.aligned.m8n8.x4.shared.b16 {%0,%1,%2,%3}, [%4];"
        : "=r"(r[0]), "=r"(r[1]), "=r"(r[2]), "=r"(r[3]) : "r"(addr));
}
__device__ __forceinline__ void ldsm4t(uint32_t* r, uint32_t addr) {
    asm volatile("ldmatrix.sync.aligned.m8n8.x4.trans.shared.b16 {%0,%1,%2,%3}, [%4];"
        : "=r"(r[0]), "=r"(r[1]), "=r"(r[2]), "=r"(r[3]) : "r"(addr));
}
__device__ __forceinline__ uint32_t packh2(float a, float b) {
    __half2 h = __floats2half2_rn(a, b);
    return *(uint32_t*)&h;
}

// smem tile: 128 rows x 64 halves (128B/row); 16B chunk c4 at r*128 + ((c4^(r&7))<<4)
#define STAGE_B 32768
#define GSMEM   (3 * STAGE_B)

__device__ __forceinline__ void issue_stage(uint32_t sbuf, const char* as, const char* ws,
                                            uint32_t w0) {
#pragma unroll
    for (int p = 0; p < 4; p++) {
        cp16(sbuf + w0 + p * 4096,         as + p * 32768);
        cp16(sbuf + 16384 + w0 + p * 4096, ws + p * 32768);
    }
}

// ---------------- mainloop: D[128m x 128c] = A[128x512] x W[128x512]^T -------
__device__ __forceinline__ void gemm_mainloop_h(const __half* __restrict__ A,
                                                const __half* __restrict__ W,
                                                char* smem, float acc[2][8][4],
                                                int m0, int c0) {
    uint32_t sb = smem_u32(smem);
    int tid = threadIdx.x;
    int wid = tid >> 5, lane = tid & 31;
    int warp_m = wid >> 1, warp_n = wid & 1;
    int lr = lane & 7, sel = lane >> 3;
    int selLo = sel & 1, selHi = sel >> 1;

    // ldmatrix per-lane rows
    int rA0 = warp_m * 32 + selLo * 8 + lr;            // fm=0 (fm=1: +16)
    int rB0 = warp_n * 64 + selLo * 8 + lr;            // jp=0 (jp: +16*jp)

    const char* Ab = (const char*)(A + (size_t)m0 * 512);
    const char* Wb = (const char*)(W + (size_t)c0 * 512);
    int r0 = tid >> 3, c4w = tid & 7;
    uint32_t w0 = (uint32_t)(r0 * 128 + ((c4w ^ (r0 & 7)) << 4));
    uint32_t so = (uint32_t)(r0 * 1024 + c4w * 16);

    issue_stage(sb,           Ab + so,       Wb + so,       w0); CP_COMMIT();
    issue_stage(sb + STAGE_B, Ab + so + 128, Wb + so + 128, w0); CP_COMMIT();

    for (int s = 0; s < 8; s++) {
        if (s + 2 < 8)
            issue_stage(sb + ((s + 2) % 3) * STAGE_B,
                        Ab + so + (s + 2) * 128, Wb + so + (s + 2) * 128, w0);
        CP_COMMIT();
        CP_WAIT2();
        __syncthreads();

        uint32_t baseA = sb + (s % 3) * STAGE_B;
        uint32_t baseB = baseA + 16384;
#pragma unroll
        for (int kk = 0; kk < 4; kk++) {
            int chunk = 2 * kk + selHi;
            uint32_t af[2][4];
#pragma unroll
            for (int fm = 0; fm < 2; fm++) {
                int r = rA0 + fm * 16;
                ldsm4(af[fm], baseA + (uint32_t)(r * 128 + ((chunk ^ (r & 7)) << 4)));
            }
#pragma unroll
            for (int jp = 0; jp < 4; jp++) {
                int r = rB0 + jp * 16;
                uint32_t bt[4];
                ldsm4(bt, baseB + (uint32_t)(r * 128 + ((chunk ^ (r & 7)) << 4)));
                uint32_t b0[2] = { bt[0], bt[2] };
                uint32_t b1[2] = { bt[1], bt[3] };
                mma_f16(acc[0][2 * jp],     af[0], b0);
                mma_f16(acc[1][2 * jp],     af[1], b0);
                mma_f16(acc[0][2 * jp + 1], af[0], b1);
                mma_f16(acc[1][2 * jp + 1], af[1], b1);
            }
        }
        __syncthreads();
    }
}

// ---------------- QKV projection (+bias, +rope), half out (b,n,c) ------------
__global__ __launch_bounds__(256)
void gemm_qkv_h(const __half* __restrict__ A, const __half* __restrict__ W,
                const float* __restrict__ bias, __half* __restrict__ Out, int do_rope) {
    extern __shared__ char smem[];
    int m0 = blockIdx.x * 128, c0 = blockIdx.y * 128;
    float acc[2][8][4];
#pragma unroll
    for (int a = 0; a < 2; a++)
#pragma unroll
        for (int j = 0; j < 8; j++)
#pragma unroll
            for (int q = 0; q < 4; q++) acc[a][j][q] = 0.f;

    gemm_mainloop_h(A, W, smem, acc, m0, c0);

    int tid = threadIdx.x;
    int wid = tid >> 5, lane = tid & 31;
    int gid = lane >> 2, tg = lane & 3;
    int warp_m = wid >> 1, warp_n = wid & 1;

#pragma unroll
    for (int fm = 0; fm < 2; fm++) {
#pragma unroll
        for (int rr = 0; rr < 2; rr++) {
            int m = m0 + warp_m * 32 + fm * 16 + gid + rr * 8;
            int n = m & (Nn - 1);
            __half* orow = Out + (size_t)m * 512;
            const float* rp = g_rope + n * 64;
#pragma unroll
            for (int j = 0; j < 8; j++) {
                int col = c0 + warp_n * 64 + j * 8 + 2 * tg;
                float v0 = acc[fm][j][rr * 2]     + __ldg(bias + col);
                float v1 = acc[fm][j][rr * 2 + 1] + __ldg(bias + col + 1);
                if (do_rope) {
                    int d = (j * 8 + 2 * tg);
                    float sn = rp[d], cs = rp[d + 1];
                    float x0 = v0, x1 = v1;
                    v0 = x0 * cs - x1 * sn;
                    v1 = x0 * sn + x1 * cs;
                }
                *(__half2*)(orow + col) = __floats2half2_rn(v0, v1);
            }
        }
    }
}

// ---------------- output projection: fp32 (b,c,n) + bias + residual ----------
#define SSTR 132
__global__ __launch_bounds__(256)
void gemm_out_h(const __half* __restrict__ A, const __half* __restrict__ W,
                const float* __restrict__ bo, const float* __restrict__ resid,
                float* __restrict__ Out) {
    extern __shared__ char smem[];
    int m0 = blockIdx.x * 128, c0 = blockIdx.y * 128;
    float acc[2][8][4];
#pragma unroll
    for (int a = 0; a < 2; a++)
#pragma unroll
        for (int j = 0; j < 8; j++)
#pragma unroll
            for (int q = 0; q < 4; q++) acc[a][j][q] = 0.f;

    gemm_mainloop_h(A, W, smem, acc, m0, c0);

    int tid = threadIdx.x;
    int wid = tid >> 5, lane = tid & 31;
    int gid = lane >> 2, tg = lane & 3;
    int warp_m = wid >> 1, warp_n = wid & 1;

    float* stage = (float*)smem;
    __syncthreads();
#pragma unroll
    for (int fm = 0; fm < 2; fm++) {
        int mb = warp_m * 32 + fm * 16 + gid;
#pragma unroll
        for (int j = 0; j < 8; j++) {
            int cl = warp_n * 64 + j * 8 + 2 * tg;
            stage[(cl    ) * SSTR + mb    ] = acc[fm][j][0];
            stage[(cl + 1) * SSTR + mb    ] = acc[fm][j][1];
            stage[(cl    ) * SSTR + mb + 8] = acc[fm][j][2];
            stage[(cl + 1) * SSTR + mb + 8] = acc[fm][j][3];
        }
    }
    __syncthreads();

    int b = m0 >> 12, n0 = m0 & (Nn - 1);
    for (int t = tid; t < 128 * 32; t += 256) {
        int cl = t >> 5, mq = (t & 31) * 4;
        int c = c0 + cl;
        float bc = __ldg(bo + c);
        size_t o = ((size_t)(b * 512 + c)) * 4096 + n0 + mq;
        float4 dv = *(float4*)(stage + cl * SSTR + mq);
        float4 rv = *(const float4*)(resid + o);
        *(float4*)(Out + o) = make_float4(dv.x + bc + rv.x, dv.y + bc + rv.y,
                                          dv.z + bc + rv.z, dv.w + bc + rv.w);
    }
}

// ---------------- weight fp32 -> half ----------------------------------------
__global__ void w2h(const float* __restrict__ src, __half* __restrict__ dst) {
    int i = (blockIdx.x * 256 + threadIdx.x) * 4;
    float4 v = *(const float4*)(src + i);
    *(__half2*)(dst + i)     = __floats2half2_rn(v.x, v.y);
    *(__half2*)(dst + i + 2) = __floats2half2_rn(v.z, v.w);
}

// ---------------- rope table -------------------------------------------------
__global__ void rope_fill() {
    int idx = blockIdx.x * blockDim.x + threadIdx.x;
    int n = idx >> 5, j = idx & 31;
    float inv = 1.0f / powf(10000.0f, (float)(2 * j) / 64.0f);
    float ang = (float)n * inv;
    g_rope[n * 64 + 2 * j]     = sinf(ang);
    g_rope[n * 64 + 2 * j + 1] = cosf(ang);
}

// ---------------- layernorm (B,C,N) -> (B,C,N) fp32 --------------------------
__global__ void ln_kernel(const float* __restrict__ x, const float* __restrict__ gam,
                          const float* __restrict__ bet, float* __restrict__ out) {
    __shared__ float gs[512], bs[512];
    int tid = threadIdx.x;
    for (int c = tid; c < 512; c += 128) { gs[c] = gam[c]; bs[c] = bet[c]; }
    __syncthreads();
    int b = blockIdx.y;
    int n = blockIdx.x * 128 + tid;
    const float* xp = x + (size_t)b * Cch * Nn + n;
    float s = 0.f, sq = 0.f;
#pragma unroll 8
    for (int c = 0; c < 512; c++) { float v = xp[(size_t)c * Nn]; s += v; sq += v * v; }
    float mu = s * (1.0f / 512.0f);
    float var = sq * (1.0f / 512.0f) - mu * mu;
    float rstd = rsqrtf(var + 1e-5f);
    float* op = out + (size_t)b * Cch * Nn + n;
#pragma unroll 8
    for (int c = 0; c < 512; c++) {
        float v = xp[(size_t)c * Nn];
        op[(size_t)c * Nn] = (v - mu) * rstd * gs[c] + bs[c];
    }
}

// ---------------- transpose (b,c,n) fp32 -> (b,n,c) half ---------------------
__global__ void transpose_cn_nc_h(const float* __restrict__ in, __half* __restrict__ out) {
    __shared__ float t[32][33];
    int b = blockIdx.z;
    int n0 = blockIdx.x * 32, c0 = blockIdx.y * 32;
    int tx = threadIdx.x, ty = threadIdx.y;
    const float* ip = in + (size_t)b * Cch * Nn;
#pragma unroll
    for (int i = 0; i < 4; i++)
        t[ty + i * 8][tx] = ip[(size_t)(c0 + ty + i * 8) * Nn + n0 + tx];
    __syncthreads();
    __half* op = out + (size_t)b * Nn * Cch;
#pragma unroll
    for (int i = 0; i < 4; i++)
        op[(size_t)(n0 + ty + i * 8) * Cch + c0 + tx] = __float2half_rn(t[tx][ty + i * 8]);
}

// ---------------- windowed attention on tensor cores -------------------------
// block = (window 0..511, head 0..7), 128 threads (4 warps), warp = 16 q-rows
__global__ __launch_bounds__(128)
void attn_mma(const float* __restrict__ bias_table) {
    __shared__ __align__(16) char sQ[8192];
    __shared__ __align__(16) char sK[8192];
    __shared__ __align__(16) char sV[8192];
    __shared__ float tbl[232];

    int tid = threadIdx.x;
    int w = blockIdx.x, h = blockIdx.y;
    int b = w >> 6, win = w & 63;
    int wy = win >> 3, wx = win & 7;

    for (int t = tid; t < 225; t += 128) tbl[t] = bias_table[t * 8 + h];

    uint32_t uQ = smem_u32(sQ), uK = smem_u32(sK), uV = smem_u32(sV);

    // gather Q/K/V rows (each 128B contiguous) into swizzled smem via cp.async
    const size_t baseC = ((size_t)b * Nn) * Cch + h * 64;   // halves
#pragma unroll
    for (int p = 0; p < 4; p++) {
        int t = p * 128 + tid;
        int r = t >> 3, c4 = t & 7;
        int ri = r >> 3, ci = r & 7;
        int n = (wy * 8 + ri) * 64 + wx * 8 + ci;
        const char* src = (const char*)(g_Qh + baseC + (size_t)n * 512) + c4 * 16;
        const char* srk = (const char*)(g_Kh + baseC + (size_t)n * 512) + c4 * 16;
        const char* srv = (const char*)(g_Vh + baseC + (size_t)n * 512) + c4 * 16;
        uint32_t dst = (uint32_t)(r * 128 + ((c4 ^ (r & 7)) << 4));
        cp16(uQ + dst, src);
        cp16(uK + dst, srk);
        cp16(uV + dst, srv);
    }
    CP_COMMIT();
    CP_WAIT0();
    __syncthreads();

    int wid = tid >> 5, lane = tid & 31;
    int gid = lane >> 2, tg = lane & 3;
    int lr = lane & 7, sel = lane >> 3;
    int selLo = sel & 1, selHi = sel >> 1;
    int m0 = wid * 16;

    int rAq = m0 + selLo * 8 + lr;           // Q ldmatrix row
    int rB0 = selLo * 8 + lr;                // K/V ldmatrix row base

    // ---- S = Q K^T ----
    float sacc[8][4];
#pragma unroll
    for (int j = 0; j < 8; j++)
#pragma unroll
        for (int q = 0; q < 4; q++) sacc[j][q] = 0.f;

#pragma unroll
    for (int kk = 0; kk < 4; kk++) {
        int chunk = 2 * kk + selHi;
        uint32_t af[4];
        ldsm4(af, uQ + (uint32_t)(rAq * 128 + ((chunk ^ (rAq & 7)) << 4)));
#pragma unroll
        for (int jp = 0; jp < 4; jp++) {
            int r = rB0 + jp * 16;
            uint32_t bt[4];
            ldsm4(bt, uK + (uint32_t)(r * 128 + ((chunk ^ (r & 7)) << 4)));
            uint32_t b0[2] = { bt[0], bt[2] };
            uint32_t b1[2] = { bt[1], bt[3] };
            mma_f16(sacc[2 * jp],     af, b0);
            mma_f16(sacc[2 * jp + 1], af, b1);
        }
    }

    // ---- scale + relative bias ----
    int iLo = m0 + gid, iHi = iLo + 8;
    int riLo = iLo >> 3, ciLo = iLo & 7, riHi = iHi >> 3, ciHi = iHi & 7;
#pragma unroll
    for (int j = 0; j < 8; j++) {
#pragma unroll
        for (int q = 0; q < 4; q++) {
            int jc = j * 8 + 2 * tg + (q & 1);
            int rj = jc >> 3, cj = jc & 7;
            int ri = (q < 2) ? riLo : riHi;
            int ci = (q < 2) ? ciLo : ciHi;
            int idx = (ri - rj + 7) * 15 + (ci - cj + 7);
            sacc[j][q] = sacc[j][q] * 0.125f + tbl[idx];
        }
    }

    // ---- softmax in registers (rows iLo, iHi; spread across 4 tg lanes) ----
    float mx0 = -1e30f, mx1 = -1e30f;
#pragma unroll
    for (int j = 0; j < 8; j++) {
        mx0 = fmaxf(mx0, fmaxf(sacc[j][0], sacc[j][1]));
        mx1 = fmaxf(mx1, fmaxf(sacc[j][2], sacc[j][3]));
    }
    mx0 = fmaxf(mx0, __shfl_xor_sync(0xffffffffu, mx0, 1));
    mx0 = fmaxf(mx0, __shfl_xor_sync(0xffffffffu, mx0, 2));
    mx1 = fmaxf(mx1, __shfl_xor_sync(0xffffffffu, mx1, 1));
    mx1 = fmaxf(mx1, __shfl_xor_sync(0xffffffffu, mx1, 2));
    float s0 = 0.f, s1 = 0.f;
#pragma unroll
    for (int j = 0; j < 8; j++) {
        sacc[j][0] = __expf(sacc[j][0] - mx0);
        sacc[j][1] = __expf(sacc[j][1] - mx0);
        sacc[j][2] = __expf(sacc[j][2] - mx1);
        sacc[j][3] = __expf(sacc[j][3] - mx1);
        s0 += sacc[j][0] + sacc[j][1];
        s1 += sacc[j][2] + sacc[j][3];
    }
    s0 += __shfl_xor_sync(0xffffffffu, s0, 1);
    s0 += __shfl_xor_sync(0xffffffffu, s0, 2);
    s1 += __shfl_xor_sync(0xffffffffu, s1, 1);
    s1 += __shfl_xor_sync(0xffffffffu, s1, 2);
    float i0v = 1.0f / s0, i1v = 1.0f / s1;
#pragma unroll
    for (int j = 0; j < 8; j++) {
        sacc[j][0] *= i0v; sacc[j][1] *= i0v;
        sacc[j][2] *= i1v; sacc[j][3] *= i1v;
    }

    // ---- O = P V  (P a-frags straight from S accumulators) ----
    float oacc[8][4];
#pragma unroll
    for (int j = 0; j < 8; j++)
#pragma unroll
        for (int q = 0; q < 4; q++) oacc[j][q] = 0.f;

#pragma unroll
    for (int kkp = 0; kkp < 4; kkp++) {
        uint32_t af[4];
        af[0] = packh2(sacc[2 * kkp][0],     sacc[2 * kkp][1]);
        af[1] = packh2(sacc[2 * kkp][2],     sacc[2 * kkp][3]);
        af[2] = packh2(sacc[2 * kkp + 1][0], sacc[2 * kkp + 1][1]);
        af[3] = packh2(sacc[2 * kkp + 1][2], sacc[2 * kkp + 1][3]);
        int j0 = kkp * 16;
#pragma unroll
        for (int dp = 0; dp < 4; dp++) {
            int r = j0 + selLo * 8 + lr;
            int chunk = 2 * dp + selHi;
            uint32_t bt[4];
            ldsm4t(bt, uV + (uint32_t)(r * 128 + ((chunk ^ (r & 7)) << 4)));
            uint32_t b0[2] = { bt[0], bt[1] };
            uint32_t b1[2] = { bt[2], bt[3] };
            mma_f16(oacc[2 * dp],     af, b0);
            mma_f16(oacc[2 * dp + 1], af, b1);
        }
    }

    // ---- store O (half, (b,n,c)) ----
    int nLo = (wy * 8 + riLo) * 64 + wx * 8 + ciLo;
    int nHi = (wy * 8 + riHi) * 64 + wx * 8 + ciHi;
    __half* oLo = g_attn_h + baseC + (size_t)nLo * 512;
    __half* oHi = g_attn_h + baseC + (size_t)nHi * 512;
#pragma unroll
    for (int dc = 0; dc < 8; dc++) {
        int d = dc * 8 + 2 * tg;
        __half2 hLo = __floats2half2_rn(oacc[dc][0], oacc[dc][1]);
        __half2 hHi = __floats2half2_rn(oacc[dc][2], oacc[dc][3]);
        *(__half2*)(oLo + d) = hLo;
        *(__half2*)(oHi + d) = hHi;
    }
}

// ---------------- launch -----------------------------------------------------
extern "C" void kernel_launch(void* const* d_in, const int* in_sizes, int n_in,
                              void* d_out, int out_size) {
    const float* q          = (const float*)d_in[0];
    const float* kv         = (const float*)d_in[1];
    const float* gq         = (const float*)d_in[2];
    const float* bqln       = (const float*)d_in[3];
    const float* gkv        = (const float*)d_in[4];
    const float* bkvln      = (const float*)d_in[5];
    const float* Wq         = (const float*)d_in[6];
    const float* bq         = (const float*)d_in[7];
    const float* Wk         = (const float*)d_in[8];
    const float* bk         = (const float*)d_in[9];
    const float* Wv         = (const float*)d_in[10];
    const float* bv         = (const float*)d_in[11];
    const float* Wo         = (const float*)d_in[12];
    const float* bo         = (const float*)d_in[13];
    const float* bias_table = (const float*)d_in[14];
    float* out = (float*)d_out;

    float  *p_qn, *p_kvn;
    __half *p_qnt, *p_kvnt, *p_Q, *p_K, *p_V, *p_attn, *p_Wh;
    cudaGetSymbolAddress((void**)&p_qn,   g_qn);
    cudaGetSymbolAddress((void**)&p_kvn,  g_kvn);
    cudaGetSymbolAddress((void**)&p_qnt,  g_qnt_h);
    cudaGetSymbolAddress((void**)&p_kvnt, g_kvnt_h);
    cudaGetSymbolAddress((void**)&p_Q,    g_Qh);
    cudaGetSymbolAddress((void**)&p_K,    g_Kh);
    cudaGetSymbolAddress((void**)&p_V,    g_Vh);
    cudaGetSymbolAddress((void**)&p_attn, g_attn_h);
    cudaGetSymbolAddress((void**)&p_Wh,   g_Wh);

    cudaFuncSetAttribute(gemm_qkv_h, cudaFuncAttributeMaxDynamicSharedMemorySize, GSMEM);
    cudaFuncSetAttribute(gemm_out_h, cudaFuncAttributeMaxDynamicSharedMemorySize, GSMEM);

    const int WB = (Cch * Cch) / 4 / 256;
    w2h<<<WB, 256>>>(Wq, p_Wh + 0 * Cch * Cch);
    w2h<<<WB, 256>>>(Wk, p_Wh + 1 * Cch * Cch);
    w2h<<<WB, 256>>>(Wv, p_Wh + 2 * Cch * Cch);
    w2h<<<WB, 256>>>(Wo, p_Wh + 3 * Cch * Cch);

    rope_fill<<<512, 256>>>();

    ln_kernel<<<dim3(Nn / 128, Bb), 128>>>(q,  gq,  bqln,  p_qn);
    ln_kernel<<<dim3(Nn / 128, Bb), 128>>>(kv, gkv, bkvln, p_kvn);

    dim3 tgrid(Nn / 32, Cch / 32, Bb);
    transpose_cn_nc_h<<<tgrid, dim3(32, 8)>>>(p_qn,  p_qnt);
    transpose_cn_nc_h<<<tgrid, dim3(32, 8)>>>(p_kvn, p_kvnt);

    dim3 ggrid(Bb * Nn / 128, Cch / 128);
    gemm_qkv_h<<<ggrid, 256, GSMEM>>>(p_qnt,  p_Wh + 0 * Cch * Cch, bq, p_Q, 1);
    gemm_qkv_h<<<ggrid, 256, GSMEM>>>(p_kvnt, p_Wh + 1 * Cch * Cch, bk, p_K, 1);
    gemm_qkv_h<<<ggrid, 256, GSMEM>>>(p_kvnt, p_Wh + 2 * Cch * Cch, bv, p_V, 0);

    attn_mma<<<dim3(Bb * 64, NHh), 128>>>(bias_table);

    gemm_out_h<<<ggrid, 256, GSMEM>>>(p_attn, p_Wh + 3 * Cch * Cch, bo, p_qn, out);
}

// round 9
// speedup vs baseline: 5.6654x; 1.1861x over previous
#include <cuda_runtime.h>
#include <cuda_fp16.h>
#include <cstdint>
#include <math.h>

#define Bb   8
#define Cch  512
#define Nn   4096
#define NHh  8
#define Dd   64

// ---------------- scratch ----------------------------------------------------
__device__ float  g_qn    [Bb*Cch*Nn];   // normalized q, (b,c,n) fp32 (residual)
__device__ __half g_qnt_h [Bb*Nn*Cch];   // normalized q , (b,n,c) half
__device__ __half g_kvnt_h[Bb*Nn*Cch];   // normalized kv, (b,n,c) half
__device__ __half g_Qh    [Bb*Nn*Cch];   // (b,n,c) after rope
__device__ __half g_Kh    [Bb*Nn*Cch];
__device__ __half g_Vh    [Bb*Nn*Cch];
__device__ __half g_attn_h[Bb*Nn*Cch];   // attention out, (b,n,c)
__device__ __half g_Wh    [4*Cch*Cch];   // rounded weights: Wq,Wk,Wv,Wo
__device__ float  g_rope  [Nn*Dd];

// ---------------- PTX helpers ------------------------------------------------
__device__ __forceinline__ uint32_t smem_u32(const void* p) {
    uint32_t a;
    asm("{ .reg .u64 t; cvta.to.shared.u64 t, %1; cvt.u32.u64 %0, t; }" : "=r"(a) : "l"(p));
    return a;
}
__device__ __forceinline__ void cp16(uint32_t dst, const void* src) {
    asm volatile("cp.async.cg.shared.global [%0], [%1], 16;" :: "r"(dst), "l"(src));
}
#define CP_COMMIT() asm volatile("cp.async.commit_group;" ::: "memory")
#define CP_WAIT2()  asm volatile("cp.async.wait_group 2;" ::: "memory")
#define CP_WAIT0()  asm volatile("cp.async.wait_group 0;" ::: "memory")

__device__ __forceinline__ void mma_f16(float* d, const uint32_t* a, const uint32_t* b) {
    asm volatile(
        "mma.sync.aligned.m16n8k16.row.col.f32.f16.f16.f32 "
        "{%0,%1,%2,%3}, {%4,%5,%6,%7}, {%8,%9}, {%0,%1,%2,%3};"
        : "+f"(d[0]), "+f"(d[1]), "+f"(d[2]), "+f"(d[3])
        : "r"(a[0]), "r"(a[1]), "r"(a[2]), "r"(a[3]), "r"(b[0]), "r"(b[1]));
}
__device__ __forceinline__ void ldsm4(uint32_t* r, uint32_t addr) {
    asm volatile("ldmatrix.sync.aligned.m8n8.x4.shared.b16 {%0,%1,%2,%3}, [%4];"
        : "=r"(r[0]), "=r"(r[1]), "=r"(r[2]), "=r"(r[3]) : "r"(addr));
}
__device__ __forceinline__ void ldsm4t(uint32_t* r, uint32_t addr) {
    asm volatile("ldmatrix.sync.aligned.m8n8.x4.trans.shared.b16 {%0,%1,%2,%3}, [%4];"
        : "=r"(r[0]), "=r"(r[1]), "=r"(r[2]), "=r"(r[3]) : "r"(addr));
}
__device__ __forceinline__ uint32_t packh2(float a, float b) {
    __half2 h = __floats2half2_rn(a, b);
    return *(uint32_t*)&h;
}

// smem tile: 128 rows x 64 halves (128B/row); 16B chunk c4 at r*128 + ((c4^(r&7))<<4)
#define STAGE_B 32768
#define GSMEM   (3 * STAGE_B)

__device__ __forceinline__ void issue_stage(uint32_t sbuf, const char* as, const char* ws,
                                            uint32_t w0) {
#pragma unroll
    for (int p = 0; p < 4; p++) {
        cp16(sbuf + w0 + p * 4096,         as + p * 32768);
        cp16(sbuf + 16384 + w0 + p * 4096, ws + p * 32768);
    }
}

// ---------------- mainloop: D[128m x 128c] = A[128x512] x W[128x512]^T -------
__device__ __forceinline__ void gemm_mainloop_h(const __half* __restrict__ A,
                                                const __half* __restrict__ W,
                                                char* smem, float acc[2][8][4],
                                                int m0, int c0) {
    uint32_t sb = smem_u32(smem);
    int tid = threadIdx.x;
    int wid = tid >> 5, lane = tid & 31;
    int warp_m = wid >> 1, warp_n = wid & 1;
    int lr = lane & 7, sel = lane >> 3;
    int selLo = sel & 1, selHi = sel >> 1;

    int rA0 = warp_m * 32 + selLo * 8 + lr;
    int rB0 = warp_n * 64 + selLo * 8 + lr;

    const char* Ab = (const char*)(A + (size_t)m0 * 512);
    const char* Wb = (const char*)(W + (size_t)c0 * 512);
    int r0 = tid >> 3, c4w = tid & 7;
    uint32_t w0 = (uint32_t)(r0 * 128 + ((c4w ^ (r0 & 7)) << 4));
    uint32_t so = (uint32_t)(r0 * 1024 + c4w * 16);

    issue_stage(sb,           Ab + so,       Wb + so,       w0); CP_COMMIT();
    issue_stage(sb + STAGE_B, Ab + so + 128, Wb + so + 128, w0); CP_COMMIT();

    for (int s = 0; s < 8; s++) {
        if (s + 2 < 8)
            issue_stage(sb + ((s + 2) % 3) * STAGE_B,
                        Ab + so + (s + 2) * 128, Wb + so + (s + 2) * 128, w0);
        CP_COMMIT();
        CP_WAIT2();
        __syncthreads();

        uint32_t baseA = sb + (s % 3) * STAGE_B;
        uint32_t baseB = baseA + 16384;
#pragma unroll
        for (int kk = 0; kk < 4; kk++) {
            int chunk = 2 * kk + selHi;
            uint32_t af[2][4];
#pragma unroll
            for (int fm = 0; fm < 2; fm++) {
                int r = rA0 + fm * 16;
                ldsm4(af[fm], baseA + (uint32_t)(r * 128 + ((chunk ^ (r & 7)) << 4)));
            }
#pragma unroll
            for (int jp = 0; jp < 4; jp++) {
                int r = rB0 + jp * 16;
                uint32_t bt[4];
                ldsm4(bt, baseB + (uint32_t)(r * 128 + ((chunk ^ (r & 7)) << 4)));
                uint32_t b0[2] = { bt[0], bt[2] };
                uint32_t b1[2] = { bt[1], bt[3] };
                mma_f16(acc[0][2 * jp],     af[0], b0);
                mma_f16(acc[1][2 * jp],     af[1], b0);
                mma_f16(acc[0][2 * jp + 1], af[0], b1);
                mma_f16(acc[1][2 * jp + 1], af[1], b1);
            }
        }
        __syncthreads();
    }
}

// ---------------- combined QKV projection (+bias, +rope), half out (b,n,c) ---
__global__ __launch_bounds__(256)
void gemm_qkv_h(const __half* __restrict__ Aq, const __half* __restrict__ Akv,
                const __half* __restrict__ Wh,
                const float* __restrict__ bqp, const float* __restrict__ bkp,
                const float* __restrict__ bvp,
                __half* __restrict__ Qo, __half* __restrict__ Ko, __half* __restrict__ Vo) {
    extern __shared__ char smem[];
    int z = blockIdx.z;
    const __half* A = z ? Akv : Aq;
    const __half* W = Wh + (size_t)z * Cch * Cch;
    const float* bias = (z == 0) ? bqp : (z == 1) ? bkp : bvp;
    __half* Out = (z == 0) ? Qo : (z == 1) ? Ko : Vo;
    int do_rope = (z < 2);

    int m0 = blockIdx.x * 128, c0 = blockIdx.y * 128;
    float acc[2][8][4];
#pragma unroll
    for (int a = 0; a < 2; a++)
#pragma unroll
        for (int j = 0; j < 8; j++)
#pragma unroll
            for (int q = 0; q < 4; q++) acc[a][j][q] = 0.f;

    gemm_mainloop_h(A, W, smem, acc, m0, c0);

    int tid = threadIdx.x;
    int wid = tid >> 5, lane = tid & 31;
    int gid = lane >> 2, tg = lane & 3;
    int warp_m = wid >> 1, warp_n = wid & 1;

#pragma unroll
    for (int fm = 0; fm < 2; fm++) {
#pragma unroll
        for (int rr = 0; rr < 2; rr++) {
            int m = m0 + warp_m * 32 + fm * 16 + gid + rr * 8;
            int n = m & (Nn - 1);
            __half* orow = Out + (size_t)m * 512;
            const float* rp = g_rope + n * 64;
#pragma unroll
            for (int j = 0; j < 8; j++) {
                int col = c0 + warp_n * 64 + j * 8 + 2 * tg;
                float v0 = acc[fm][j][rr * 2]     + __ldg(bias + col);
                float v1 = acc[fm][j][rr * 2 + 1] + __ldg(bias + col + 1);
                if (do_rope) {
                    int d = (j * 8 + 2 * tg);
                    float sn = rp[d], cs = rp[d + 1];
                    float x0 = v0, x1 = v1;
                    v0 = x0 * cs - x1 * sn;
                    v1 = x0 * sn + x1 * cs;
                }
                *(__half2*)(orow + col) = __floats2half2_rn(v0, v1);
            }
        }
    }
}

// ---------------- output projection: fp32 (b,c,n) + bias + residual ----------
#define SSTR 132
__global__ __launch_bounds__(256)
void gemm_out_h(const __half* __restrict__ A, const __half* __restrict__ W,
                const float* __restrict__ bo, const float* __restrict__ resid,
                float* __restrict__ Out) {
    extern __shared__ char smem[];
    int m0 = blockIdx.x * 128, c0 = blockIdx.y * 128;
    float acc[2][8][4];
#pragma unroll
    for (int a = 0; a < 2; a++)
#pragma unroll
        for (int j = 0; j < 8; j++)
#pragma unroll
            for (int q = 0; q < 4; q++) acc[a][j][q] = 0.f;

    gemm_mainloop_h(A, W, smem, acc, m0, c0);

    int tid = threadIdx.x;
    int wid = tid >> 5, lane = tid & 31;
    int gid = lane >> 2, tg = lane & 3;
    int warp_m = wid >> 1, warp_n = wid & 1;

    float* stage = (float*)smem;
    __syncthreads();
#pragma unroll
    for (int fm = 0; fm < 2; fm++) {
        int mb = warp_m * 32 + fm * 16 + gid;
#pragma unroll
        for (int j = 0; j < 8; j++) {
            int cl = warp_n * 64 + j * 8 + 2 * tg;
            stage[(cl    ) * SSTR + mb    ] = acc[fm][j][0];
            stage[(cl + 1) * SSTR + mb    ] = acc[fm][j][1];
            stage[(cl    ) * SSTR + mb + 8] = acc[fm][j][2];
            stage[(cl + 1) * SSTR + mb + 8] = acc[fm][j][3];
        }
    }
    __syncthreads();

    int b = m0 >> 12, n0 = m0 & (Nn - 1);
    for (int t = tid; t < 128 * 32; t += 256) {
        int cl = t >> 5, mq = (t & 31) * 4;
        int c = c0 + cl;
        float bc = __ldg(bo + c);
        size_t o = ((size_t)(b * 512 + c)) * 4096 + n0 + mq;
        float4 dv = *(float4*)(stage + cl * SSTR + mq);
        float4 rv = *(const float4*)(resid + o);
        *(float4*)(Out + o) = make_float4(dv.x + bc + rv.x, dv.y + bc + rv.y,
                                          dv.z + bc + rv.z, dv.w + bc + rv.w);
    }
}

// ---------------- all-weights fp32 -> half (one launch) ----------------------
__global__ void w2h_all(const float* __restrict__ w0, const float* __restrict__ w1,
                        const float* __restrict__ w2, const float* __restrict__ w3,
                        __half* __restrict__ dst) {
    int wsel = blockIdx.y;
    const float* src = (wsel == 0) ? w0 : (wsel == 1) ? w1 : (wsel == 2) ? w2 : w3;
    int i = (blockIdx.x * 256 + threadIdx.x) * 4;
    float4 v = *(const float4*)(src + i);
    __half* d = dst + (size_t)wsel * Cch * Cch + i;
    *(__half2*)(d)     = __floats2half2_rn(v.x, v.y);
    *(__half2*)(d + 2) = __floats2half2_rn(v.z, v.w);
}

// ---------------- rope table -------------------------------------------------
__global__ void rope_fill() {
    int idx = blockIdx.x * blockDim.x + threadIdx.x;
    int n = idx >> 5, j = idx & 31;
    float inv = 1.0f / powf(10000.0f, (float)(2 * j) / 64.0f);
    float ang = (float)n * inv;
    g_rope[n * 64 + 2 * j]     = sinf(ang);
    g_rope[n * 64 + 2 * j + 1] = cosf(ang);
}

// ---------------- fused layernorm: (b,c,n) fp32 in -> (b,n,c) half out -------
// z=0: q path (also writes fp32 (b,c,n) residual); z=1: kv path
#define LSTR 72
__global__ __launch_bounds__(128)
void ln_fused(const float* __restrict__ xq, const float* __restrict__ xkv,
              const float* __restrict__ gq, const float* __restrict__ bq,
              const float* __restrict__ gkv, const float* __restrict__ bkv,
              float* __restrict__ out_qn,
              __half* __restrict__ out_qt, __half* __restrict__ out_kvt) {
    __shared__ float gs[512], bs[512];
    __shared__ __half st[128 * LSTR];
    int z = blockIdx.z;
    const float* x   = z ? xkv : xq;
    const float* gam = z ? gkv : gq;
    const float* bet = z ? bkv : bq;
    __half* outT     = z ? out_kvt : out_qt;

    int tid = threadIdx.x;
    for (int c = tid; c < 512; c += 128) { gs[c] = gam[c]; bs[c] = bet[c]; }
    __syncthreads();

    int b = blockIdx.y;
    int n0 = blockIdx.x * 128;
    int n = n0 + tid;
    const float* xp = x + (size_t)b * Cch * Nn + n;

    float s = 0.f, sq = 0.f;
#pragma unroll 8
    for (int c = 0; c < 512; c++) { float v = xp[(size_t)c * Nn]; s += v; sq += v * v; }
    float mu   = s * (1.0f / 512.0f);
    float var  = sq * (1.0f / 512.0f) - mu * mu;
    float rstd = rsqrtf(var + 1e-5f);

    float* op32 = out_qn + (size_t)b * Cch * Nn + n;
    __half* obase = outT + ((size_t)b * Nn + n0) * 512;

    for (int ch = 0; ch < 8; ch++) {
#pragma unroll
        for (int cc = 0; cc < 64; cc += 2) {
            int c = ch * 64 + cc;
            float v0 = xp[(size_t)c * Nn];
            float v1 = xp[(size_t)(c + 1) * Nn];
            float y0 = (v0 - mu) * rstd * gs[c]     + bs[c];
            float y1 = (v1 - mu) * rstd * gs[c + 1] + bs[c + 1];
            if (z == 0) {
                op32[(size_t)c * Nn]       = y0;
                op32[(size_t)(c + 1) * Nn] = y1;
            }
            *(__half2*)(st + tid * LSTR + cc) = __floats2half2_rn(y0, y1);
        }
        __syncthreads();
        // write 128 rows x 128B (each row: token n0+r, channels ch*64..+63)
        for (int t = tid; t < 1024; t += 128) {
            int r = t >> 3, c4 = t & 7;
            *(uint4*)(obase + (size_t)r * 512 + ch * 64 + c4 * 8) =
                *(uint4*)(st + r * LSTR + c4 * 8);
        }
        __syncthreads();
    }
}

// ---------------- windowed attention on tensor cores -------------------------
__global__ __launch_bounds__(128)
void attn_mma(const float* __restrict__ bias_table) {
    __shared__ __align__(16) char sQ[8192];
    __shared__ __align__(16) char sK[8192];
    __shared__ __align__(16) char sV[8192];
    __shared__ float tbl[232];

    int tid = threadIdx.x;
    int w = blockIdx.x, h = blockIdx.y;
    int b = w >> 6, win = w & 63;
    int wy = win >> 3, wx = win & 7;

    for (int t = tid; t < 225; t += 128) tbl[t] = bias_table[t * 8 + h];

    uint32_t uQ = smem_u32(sQ), uK = smem_u32(sK), uV = smem_u32(sV);

    const size_t baseC = ((size_t)b * Nn) * Cch + h * 64;
#pragma unroll
    for (int p = 0; p < 4; p++) {
        int t = p * 128 + tid;
        int r = t >> 3, c4 = t & 7;
        int ri = r >> 3, ci = r & 7;
        int n = (wy * 8 + ri) * 64 + wx * 8 + ci;
        const char* src = (const char*)(g_Qh + baseC + (size_t)n * 512) + c4 * 16;
        const char* srk = (const char*)(g_Kh + baseC + (size_t)n * 512) + c4 * 16;
        const char* srv = (const char*)(g_Vh + baseC + (size_t)n * 512) + c4 * 16;
        uint32_t dst = (uint32_t)(r * 128 + ((c4 ^ (r & 7)) << 4));
        cp16(uQ + dst, src);
        cp16(uK + dst, srk);
        cp16(uV + dst, srv);
    }
    CP_COMMIT();
    CP_WAIT0();
    __syncthreads();

    int wid = tid >> 5, lane = tid & 31;
    int gid = lane >> 2, tg = lane & 3;
    int lr = lane & 7, sel = lane >> 3;
    int selLo = sel & 1, selHi = sel >> 1;
    int m0 = wid * 16;

    int rAq = m0 + selLo * 8 + lr;
    int rB0 = selLo * 8 + lr;

    float sacc[8][4];
#pragma unroll
    for (int j = 0; j < 8; j++)
#pragma unroll
        for (int q = 0; q < 4; q++) sacc[j][q] = 0.f;

#pragma unroll
    for (int kk = 0; kk < 4; kk++) {
        int chunk = 2 * kk + selHi;
        uint32_t af[4];
        ldsm4(af, uQ + (uint32_t)(rAq * 128 + ((chunk ^ (rAq & 7)) << 4)));
#pragma unroll
        for (int jp = 0; jp < 4; jp++) {
            int r = rB0 + jp * 16;
            uint32_t bt[4];
            ldsm4(bt, uK + (uint32_t)(r * 128 + ((chunk ^ (r & 7)) << 4)));
            uint32_t b0[2] = { bt[0], bt[2] };
            uint32_t b1[2] = { bt[1], bt[3] };
            mma_f16(sacc[2 * jp],     af, b0);
            mma_f16(sacc[2 * jp + 1], af, b1);
        }
    }

    int iLo = m0 + gid, iHi = iLo + 8;
    int riLo = iLo >> 3, ciLo = iLo & 7, riHi = iHi >> 3, ciHi = iHi & 7;
#pragma unroll
    for (int j = 0; j < 8; j++) {
#pragma unroll
        for (int q = 0; q < 4; q++) {
            int jc = j * 8 + 2 * tg + (q & 1);
            int rj = jc >> 3, cj = jc & 7;
            int ri = (q < 2) ? riLo : riHi;
            int ci = (q < 2) ? ciLo : ciHi;
            int idx = (ri - rj + 7) * 15 + (ci - cj + 7);
            sacc[j][q] = sacc[j][q] * 0.125f + tbl[idx];
        }
    }

    float mx0 = -1e30f, mx1 = -1e30f;
#pragma unroll
    for (int j = 0; j < 8; j++) {
        mx0 = fmaxf(mx0, fmaxf(sacc[j][0], sacc[j][1]));
        mx1 = fmaxf(mx1, fmaxf(sacc[j][2], sacc[j][3]));
    }
    mx0 = fmaxf(mx0, __shfl_xor_sync(0xffffffffu, mx0, 1));
    mx0 = fmaxf(mx0, __shfl_xor_sync(0xffffffffu, mx0, 2));
    mx1 = fmaxf(mx1, __shfl_xor_sync(0xffffffffu, mx1, 1));
    mx1 = fmaxf(mx1, __shfl_xor_sync(0xffffffffu, mx1, 2));
    float s0 = 0.f, s1 = 0.f;
#pragma unroll
    for (int j = 0; j < 8; j++) {
        sacc[j][0] = __expf(sacc[j][0] - mx0);
        sacc[j][1] = __expf(sacc[j][1] - mx0);
        sacc[j][2] = __expf(sacc[j][2] - mx1);
        sacc[j][3] = __expf(sacc[j][3] - mx1);
        s0 += sacc[j][0] + sacc[j][1];
        s1 += sacc[j][2] + sacc[j][3];
    }
    s0 += __shfl_xor_sync(0xffffffffu, s0, 1);
    s0 += __shfl_xor_sync(0xffffffffu, s0, 2);
    s1 += __shfl_xor_sync(0xffffffffu, s1, 1);
    s1 += __shfl_xor_sync(0xffffffffu, s1, 2);
    float i0v = 1.0f / s0, i1v = 1.0f / s1;
#pragma unroll
    for (int j = 0; j < 8; j++) {
        sacc[j][0] *= i0v; sacc[j][1] *= i0v;
        sacc[j][2] *= i1v; sacc[j][3] *= i1v;
    }

    float oacc[8][4];
#pragma unroll
    for (int j = 0; j < 8; j++)
#pragma unroll
        for (int q = 0; q < 4; q++) oacc[j][q] = 0.f;

#pragma unroll
    for (int kkp = 0; kkp < 4; kkp++) {
        uint32_t af[4];
        af[0] = packh2(sacc[2 * kkp][0],     sacc[2 * kkp][1]);
        af[1] = packh2(sacc[2 * kkp][2],     sacc[2 * kkp][3]);
        af[2] = packh2(sacc[2 * kkp + 1][0], sacc[2 * kkp + 1][1]);
        af[3] = packh2(sacc[2 * kkp + 1][2], sacc[2 * kkp + 1][3]);
        int j0 = kkp * 16;
#pragma unroll
        for (int dp = 0; dp < 4; dp++) {
            int r = j0 + selLo * 8 + lr;
            int chunk = 2 * dp + selHi;
            uint32_t bt[4];
            ldsm4t(bt, uV + (uint32_t)(r * 128 + ((chunk ^ (r & 7)) << 4)));
            uint32_t b0[2] = { bt[0], bt[1] };
            uint32_t b1[2] = { bt[2], bt[3] };
            mma_f16(oacc[2 * dp],     af, b0);
            mma_f16(oacc[2 * dp + 1], af, b1);
        }
    }

    int nLo = (wy * 8 + riLo) * 64 + wx * 8 + ciLo;
    int nHi = (wy * 8 + riHi) * 64 + wx * 8 + ciHi;
    __half* oLo = g_attn_h + baseC + (size_t)nLo * 512;
    __half* oHi = g_attn_h + baseC + (size_t)nHi * 512;
#pragma unroll
    for (int dc = 0; dc < 8; dc++) {
        int d = dc * 8 + 2 * tg;
        *(__half2*)(oLo + d) = __floats2half2_rn(oacc[dc][0], oacc[dc][1]);
        *(__half2*)(oHi + d) = __floats2half2_rn(oacc[dc][2], oacc[dc][3]);
    }
}

// ---------------- launch -----------------------------------------------------
extern "C" void kernel_launch(void* const* d_in, const int* in_sizes, int n_in,
                              void* d_out, int out_size) {
    const float* q          = (const float*)d_in[0];
    const float* kv         = (const float*)d_in[1];
    const float* gq         = (const float*)d_in[2];
    const float* bqln       = (const float*)d_in[3];
    const float* gkv        = (const float*)d_in[4];
    const float* bkvln      = (const float*)d_in[5];
    const float* Wq         = (const float*)d_in[6];
    const float* bq         = (const float*)d_in[7];
    const float* Wk         = (const float*)d_in[8];
    const float* bk         = (const float*)d_in[9];
    const float* Wv         = (const float*)d_in[10];
    const float* bv         = (const float*)d_in[11];
    const float* Wo         = (const float*)d_in[12];
    const float* bo         = (const float*)d_in[13];
    const float* bias_table = (const float*)d_in[14];
    float* out = (float*)d_out;

    float  *p_qn;
    __half *p_qnt, *p_kvnt, *p_Q, *p_K, *p_V, *p_attn, *p_Wh;
    cudaGetSymbolAddress((void**)&p_qn,   g_qn);
    cudaGetSymbolAddress((void**)&p_qnt,  g_qnt_h);
    cudaGetSymbolAddress((void**)&p_kvnt, g_kvnt_h);
    cudaGetSymbolAddress((void**)&p_Q,    g_Qh);
    cudaGetSymbolAddress((void**)&p_K,    g_Kh);
    cudaGetSymbolAddress((void**)&p_V,    g_Vh);
    cudaGetSymbolAddress((void**)&p_attn, g_attn_h);
    cudaGetSymbolAddress((void**)&p_Wh,   g_Wh);

    cudaFuncSetAttribute(gemm_qkv_h, cudaFuncAttributeMaxDynamicSharedMemorySize, GSMEM);
    cudaFuncSetAttribute(gemm_out_h, cudaFuncAttributeMaxDynamicSharedMemorySize, GSMEM);

    w2h_all<<<dim3((Cch * Cch) / 4 / 256, 4), 256>>>(Wq, Wk, Wv, Wo, p_Wh);
    rope_fill<<<512, 256>>>();

    ln_fused<<<dim3(Nn / 128, Bb, 2), 128>>>(q, kv, gq, bqln, gkv, bkvln,
                                             p_qn, p_qnt, p_kvnt);

    gemm_qkv_h<<<dim3(Bb * Nn / 128, Cch / 128, 3), 256, GSMEM>>>(
        p_qnt, p_kvnt, p_Wh, bq, bk, bv, p_Q, p_K, p_V);

    attn_mma<<<dim3(Bb * 64, NHh), 128>>>(bias_table);

    gemm_out_h<<<dim3(Bb * Nn / 128, Cch / 128), 256, GSMEM>>>(
        p_attn, p_Wh + 3 * (size_t)Cch * Cch, bo, p_qn, out);
}